// round 13
// baseline (speedup 1.0000x reference)
#include <cuda_runtime.h>
#include <cuda_bf16.h>
#include <cstdint>
#include <float.h>

// Problem constants (shapes fixed by the dataset)
#define BATCH 4
#define NPT   16384
#define SPT   2048
#define KNN   16
#define DFEAT 125
#define C0    128
#define C1    128
#define C2    256
#define MROWS (BATCH * SPT * KNN)   // 131072 samples through the MLP
#define MBLK  (MROWS / 128)         // 1024 gemm m-blocks (128-row tiles)
#define PSQ_OFF (MBLK * 256)        // sumsq offset inside g_part
#define RSQ_OFF (32 * 256)          // sumsq offset inside g_red

// FPS cluster config: 8 CTAs x 256 threads per batch
#define FC 8
#define FT 256
#define FP (NPT / FC / FT)          // 8 points per thread
#define XT (FC * 8)                 // tx bytes per exchange (8 sources x 8B)
#define FPS_SMEM (3 * NPT * 4)      // full batch xyz in SMEM (192 KB)

// ---------------- scratch (static device globals; no allocation allowed) ----
__device__ float g_y1[(size_t)MROWS * C1];     // conv1 out (raw, pre-BN)
__device__ float g_max[(size_t)BATCH * SPT * C2]; // raw per-group max (8.4MB)
__device__ float g_part[2 * MBLK * 256];       // per-mblock [sum | sumsq]
__device__ float g_red[2 * 32 * 256];          // stage-1 reduced partials
__device__ float g_scale[256];
__device__ float g_bias[256];
__device__ int   g_prog[BATCH];                // FPS progress (samples done)
__device__ float g_sx[BATCH * NPT];            // SoA xyz
__device__ float g_sy[BATCH * NPT];
__device__ float g_sz[BATCH * NPT];

// ---------------------------------------------------------------------------
// helpers
// ---------------------------------------------------------------------------
__device__ __forceinline__ uint32_t smem_u32(const void* p) {
    return (uint32_t)__cvta_generic_to_shared(p);
}
__device__ __forceinline__ uint32_t mapa_u32(uint32_t addr, uint32_t rank) {
    uint32_t r;
    asm("mapa.shared::cluster.u32 %0, %1, %2;" : "=r"(r) : "r"(addr), "r"(rank));
    return r;
}
__device__ __forceinline__ void st_async_u64(uint32_t raddr, uint32_t rmbar, uint64_t v) {
    asm volatile("st.async.shared::cluster.mbarrier::complete_tx::bytes.b64 [%0], %1, [%2];"
                 :: "r"(raddr), "l"(v), "r"(rmbar) : "memory");
}
__device__ __forceinline__ void mbar_inval(uint32_t a) {
    asm volatile("mbarrier.inval.shared.b64 [%0];" :: "r"(a) : "memory");
}
__device__ __forceinline__ void mbar_init(uint32_t a, uint32_t cnt) {
    asm volatile("mbarrier.init.shared.b64 [%0], %1;" :: "r"(a), "r"(cnt) : "memory");
}
__device__ __forceinline__ void mbar_arrive_expect(uint32_t a, uint32_t tx) {
    asm volatile("mbarrier.arrive.expect_tx.shared.b64 _, [%0], %1;"
                 :: "r"(a), "r"(tx) : "memory");
}
__device__ __forceinline__ void mbar_wait(uint32_t mbar, uint32_t parity) {
    asm volatile(
        "{\n\t.reg .pred P;\n\t"
        "WAIT_%=:\n\t"
        "mbarrier.try_wait.parity.acquire.cluster.shared::cta.b64 P, [%0], %1, 0x989680;\n\t"
        "@P bra.uni DONE_%=;\n\t"
        "bra.uni WAIT_%=;\n\t"
        "DONE_%=:\n\t}"
        :: "r"(mbar), "r"(parity) : "memory");
}
__device__ __forceinline__ uint64_t u64max(uint64_t a, uint64_t b) {
    return (a > b) ? a : b;
}
__device__ __forceinline__ void st_rel_i32(int* p, int v) {
    asm volatile("st.release.gpu.global.s32 [%0], %1;" :: "l"(p), "r"(v) : "memory");
}
__device__ __forceinline__ int ld_acq_i32(const int* p) {
    int v;
    asm volatile("ld.acquire.gpu.global.s32 %0, [%1];" : "=r"(v) : "l"(p) : "memory");
    return v;
}
// L2-coherent load (bypass L1) — required for data produced by a
// CONCURRENTLY RUNNING kernel (plain ld.global can hit stale L1 lines).
__device__ __forceinline__ float ld_cg_f32(const float* p) {
    float v;
    asm volatile("ld.global.cg.f32 %0, [%1];" : "=f"(v) : "l"(p) : "memory");
    return v;
}

// ============================================================================
// 0) AoS -> SoA transpose of xyz (coalesced via smem staging) + zero progress
// ============================================================================
__global__ __launch_bounds__(256)
void soa_kernel(const float* __restrict__ xyz) {
    __shared__ float buf[768];
    int t = threadIdx.x;
    if (blockIdx.x == 0 && t < BATCH) g_prog[t] = 0;
    size_t base = (size_t)blockIdx.x * 768;
#pragma unroll
    for (int r = 0; r < 3; r++) buf[t + 256 * r] = xyz[base + t + 256 * r];
    __syncthreads();
    size_t o = (size_t)blockIdx.x * 256 + t;
    g_sx[o] = buf[t * 3 + 0];
    g_sy[o] = buf[t * 3 + 1];
    g_sz[o] = buf[t * 3 + 2];
}

// ============================================================================
// 1) FPS (R10 protocol) + progress publication + PDL trigger.
//    Single u64 key = (dist_bits << 32) | ~idx -> u64 max == jnp argmax
//    tie-break. Exact jnp semantics: no FMA contraction, selected[0] = 0.
//    After writing sample s, rank0/t0 does st.release g_prog[b] = s+1 so the
//    concurrent fused kNN+gemm1 kernel can consume samples while FPS runs.
// ============================================================================
__global__ __launch_bounds__(FT, 1) __cluster_dims__(FC, 1, 1)
void fps_cluster_kernel(float* __restrict__ new_xyz) {
    extern __shared__ float smem[];
    float* shx = smem;
    float* shy = smem + NPT;
    float* shz = smem + 2 * NPT;

    int b = blockIdx.x / FC;
    int rank = blockIdx.x % FC;
    int t = threadIdx.x;
    int w = t >> 5, lane = t & 31;
    int base = rank * (NPT / FC);
    const float* sx = g_sx + (size_t)b * NPT;
    const float* sy = g_sy + (size_t)b * NPT;
    const float* sz = g_sz + (size_t)b * NPT;

    for (int i = t; i < NPT; i += FT) {
        shx[i] = sx[i]; shy[i] = sy[i]; shz[i] = sz[i];
    }

    float px[FP], py[FP], pz[FP], dist[FP];
#pragma unroll
    for (int j = 0; j < FP; j++) {
        int i = base + j * FT + t;
        px[j] = sx[i]; py[j] = sy[i]; pz[j] = sz[i];
        dist[j] = 1e10f;
    }

    __shared__ __align__(8) uint64_t c_slot[2][FC];
    __shared__ __align__(8) uint64_t mbar[2];
    __shared__ __align__(8) uint64_t s_key[8];

    uint32_t mb0 = smem_u32(&mbar[0]);
    uint32_t mb1 = smem_u32(&mbar[1]);

    if (t == 0) {
        mbar_inval(mb0); mbar_inval(mb1);
        mbar_init(mb0, 1); mbar_init(mb1, 1);
        mbar_arrive_expect(mb0, 0);
        mbar_arrive_expect(mb0, XT);
        mbar_arrive_expect(mb1, XT);
    }
    __syncthreads();
    asm volatile("barrier.cluster.arrive.aligned;" ::: "memory");
    asm volatile("barrier.cluster.wait.aligned;" ::: "memory");

    // all FPS CTAs are resident now -> allow the fused kernel to dispatch
    if (t == 0) cudaTriggerProgrammaticLaunchCompletion();

    uint32_t r_s0 = 0, r_s1 = 0, r_m0 = 0, r_m1 = 0;
    if (w == 0 && lane < FC) {
        r_s0 = mapa_u32(smem_u32(&c_slot[0][rank]), lane);
        r_s1 = mapa_u32(smem_u32(&c_slot[1][rank]), lane);
        r_m0 = mapa_u32(mb0, lane);
        r_m1 = mapa_u32(mb1, lane);
    }

    float curx = shx[0], cury = shy[0], curz = shz[0];
    float* out = new_xyz + (size_t)b * SPT * 3;

    for (int s = 0; s < SPT; s++) {
        if (s > 0) {
            uint32_t mb = (s & 1) ? mb1 : mb0;
            mbar_wait(mb, (unsigned)((s >> 1) & 1));
            int bf = s & 1;
            uint64_t k0 = c_slot[bf][0], k1 = c_slot[bf][1];
            uint64_t k2 = c_slot[bf][2], k3 = c_slot[bf][3];
            uint64_t k4 = c_slot[bf][4], k5 = c_slot[bf][5];
            uint64_t k6 = c_slot[bf][6], k7 = c_slot[bf][7];
            uint64_t wk = u64max(u64max(u64max(k0, k1), u64max(k2, k3)),
                                 u64max(u64max(k4, k5), u64max(k6, k7)));
            int wi = (int)(~(uint32_t)wk);
            curx = shx[wi]; cury = shy[wi]; curz = shz[wi];
        }
        if (rank == 0 && t == 0) {
            out[s * 3 + 0] = curx;
            out[s * 3 + 1] = cury;
            out[s * 3 + 2] = curz;
            st_rel_i32(&g_prog[b], s + 1);   // publish sample s
        }
        float best = -1.0f; int bj = 0;
#pragma unroll
        for (int j = 0; j < FP; j++) {
            float dx = px[j] - curx, dy = py[j] - cury, dz = pz[j] - curz;
            float d = __fadd_rn(__fadd_rn(__fmul_rn(dx, dx), __fmul_rn(dy, dy)),
                                __fmul_rn(dz, dz));
            float nd = fminf(dist[j], d);
            dist[j] = nd;
            bool bt = nd > best;
            best = bt ? nd : best;
            bj = bt ? j : bj;
        }
        unsigned bi = (unsigned)(base + bj * FT + t);
        unsigned vb = __float_as_uint(best);
        unsigned mv = __reduce_max_sync(0xffffffffu, vb);
        unsigned cnd = (vb == mv) ? ~bi : 0u;
        unsigned ml = __reduce_max_sync(0xffffffffu, cnd);
        if (lane == 0) s_key[w] = ((uint64_t)mv << 32) | ml;
        __syncthreads();
        if (w == 0) {
            if (s + 1 < SPT) {
                unsigned hi = (lane < 8) ? (unsigned)(s_key[lane] >> 32) : 0u;
                unsigned lo = (lane < 8) ? (unsigned)s_key[lane] : 0u;
                unsigned mv2 = __reduce_max_sync(0xffffffffu, hi);
                unsigned c2 = (hi == mv2) ? lo : 0u;
                unsigned ml2 = __reduce_max_sync(0xffffffffu, c2);
                if (lane < FC) {
                    int st = (s + 1) & 1;
                    uint32_t rs = st ? r_s1 : r_s0;
                    uint32_t rm = st ? r_m1 : r_m0;
                    st_async_u64(rs, rm, ((uint64_t)mv2 << 32) | ml2);
                }
            }
            if (lane == 8 && s > 0 && s + 2 < SPT)
                mbar_arrive_expect((s & 1) ? mb1 : mb0, XT);
        }
    }
    asm volatile("barrier.cluster.arrive.aligned;" ::: "memory");
    asm volatile("barrier.cluster.wait.aligned;" ::: "memory");
}

// ============================================================================
// 2) FUSED kNN + conv1 (PDL secondary; streams behind FPS).
//    Block m: 8 warps each spin on g_prog until their query's coords are
//    published, compute warp-collective top-16 into smem, then the block
//    runs the 128x128 gemm1 (gather rows from smem knn) with fused
//    BN1-stats partials. ALL newxyz reads use ld.global.cg — newxyz is being
//    written by the concurrently running FPS kernel and plain L1-cached
//    loads can return stale lines (R12 failure).
// ============================================================================
__global__ __launch_bounds__(256, 2)
void fused_knn_gemm1(const float* __restrict__ newxyz, const float* __restrict__ feat,
                     const float* __restrict__ W, const float* __restrict__ bias,
                     float* __restrict__ Y, float* __restrict__ part) {
    const int K = 128;
    __shared__ float As[16][128];
    __shared__ float Ws[16][128];
    __shared__ int s_idx[128];
    int tid = threadIdx.x;
    int w = tid >> 5, lane = tid & 31;
    int m0 = blockIdx.x * 128;

    // ---- Phase A: kNN for this block's 8 queries (one per warp) ----
    {
        int g = blockIdx.x * 8 + w;
        int b = g >> 11;
        int q = g & 2047;
        if (lane == 0) {
            while (ld_acq_i32(&g_prog[b]) < q + 1) __nanosleep(128);
        }
        __syncwarp();
        const float* sx = g_sx + (size_t)b * NPT;
        const float* sy = g_sy + (size_t)b * NPT;
        const float* sz = g_sz + (size_t)b * NPT;
        float qx = ld_cg_f32(&newxyz[(size_t)g * 3 + 0]);
        float qy = ld_cg_f32(&newxyz[(size_t)g * 3 + 1]);
        float qz = ld_cg_f32(&newxyz[(size_t)g * 3 + 2]);

        float tv = (lane < 16) ? FLT_MAX : 0.0f;
        int   tix = 0;
        float ww = FLT_MAX;
        for (int i = 0; i < NPT / 32; i++) {
            int base = i << 5;
            float dx = sx[base + lane] - qx;
            float dy = sy[base + lane] - qy;
            float dz = sz[base + lane] - qz;
            float d = dx * dx + dy * dy + dz * dz;
            unsigned m = __ballot_sync(0xffffffffu, d < ww);
            while (m) {
                int src = __ffs(m) - 1; m &= m - 1;
                float dc = __shfl_sync(0xffffffffu, d, src);
                if (dc < ww) {
                    unsigned mv = __reduce_max_sync(0xffffffffu, __float_as_uint(tv));
                    unsigned own = __ballot_sync(0xffffffffu, __float_as_uint(tv) == mv) & 0xffffu;
                    if (lane == __ffs(own) - 1) { tv = dc; tix = base + src; }
                    ww = __uint_as_float(__reduce_max_sync(0xffffffffu, __float_as_uint(tv)));
                }
            }
        }
        if (lane < 16) s_idx[w * 16 + lane] = tix;
    }
    __syncthreads();

    // ---- Phase B: gemm1 for rows [m0, m0+128), gather from s_idx ----
    int tx = tid & 15, ty = tid >> 4;
    int lrow = tid & 127, khalf = tid >> 7;
    int kb = khalf * 8;

    const float* gfp;
    float gx0 = 0.0f, gx1 = 0.0f, gx2 = 0.0f;
    {
        int n = m0 + lrow;
        int g = n >> 4;
        int bb = g >> 11;
        int idx = s_idx[lrow];
        size_t p = (size_t)bb * NPT + idx;
        gfp = feat + p * DFEAT;
        if (khalf == 0) {
            gx0 = g_sx[p] - ld_cg_f32(&newxyz[(size_t)g * 3 + 0]);
            gx1 = g_sy[p] - ld_cg_f32(&newxyz[(size_t)g * 3 + 1]);
            gx2 = g_sz[p] - ld_cg_f32(&newxyz[(size_t)g * 3 + 2]);
        }
    }

    float acc[8][8];
#pragma unroll
    for (int i = 0; i < 8; i++)
#pragma unroll
        for (int j = 0; j < 8; j++) acc[i][j] = 0.0f;

    float ar[8];
#pragma unroll
    for (int u = 0; u < 8; u++) {
        int cc = kb + u - 3;
        ar[u] = gfp[cc < 0 ? 0 : cc];
    }
    if (khalf == 0) { ar[0] = gx0; ar[1] = gx1; ar[2] = gx2; }

    for (int kt = 0; kt < 8; kt++) {
        int k0 = kt * 16;
#pragma unroll
        for (int u = 0; u < 8; u++) As[kb + u][lrow] = ar[u];
        {
            const float* wp = &W[(size_t)lrow * K + k0 + kb];
            float4 w0 = *(const float4*)wp;
            float4 w1 = *(const float4*)(wp + 4);
            Ws[kb + 0][lrow] = w0.x; Ws[kb + 1][lrow] = w0.y;
            Ws[kb + 2][lrow] = w0.z; Ws[kb + 3][lrow] = w0.w;
            Ws[kb + 4][lrow] = w1.x; Ws[kb + 5][lrow] = w1.y;
            Ws[kb + 6][lrow] = w1.z; Ws[kb + 7][lrow] = w1.w;
        }
        __syncthreads();
        if (kt < 7) {
            int kn = k0 + 16;
#pragma unroll
            for (int u = 0; u < 8; u++) ar[u] = gfp[kn + kb + u - 3];
        }
#pragma unroll
        for (int kk = 0; kk < 16; kk++) {
            float4 xa0 = *(const float4*)&As[kk][ty * 8];
            float4 xa1 = *(const float4*)&As[kk][ty * 8 + 4];
            float4 xb0 = *(const float4*)&Ws[kk][tx * 8];
            float4 xb1 = *(const float4*)&Ws[kk][tx * 8 + 4];
            float av[8] = {xa0.x, xa0.y, xa0.z, xa0.w, xa1.x, xa1.y, xa1.z, xa1.w};
            float bv[8] = {xb0.x, xb0.y, xb0.z, xb0.w, xb1.x, xb1.y, xb1.z, xb1.w};
#pragma unroll
            for (int i = 0; i < 8; i++)
#pragma unroll
                for (int j = 0; j < 8; j++) acc[i][j] += av[i] * bv[j];
        }
        __syncthreads();
    }
#pragma unroll
    for (int i = 0; i < 8; i++)
#pragma unroll
        for (int j = 0; j < 8; j++) acc[i][j] += bias[tx * 8 + j];

#pragma unroll
    for (int i = 0; i < 8; i++) {
        size_t row = (size_t)(m0 + ty * 8 + i) * C1 + tx * 8;
        float4 v0 = {acc[i][0], acc[i][1], acc[i][2], acc[i][3]};
        float4 v1 = {acc[i][4], acc[i][5], acc[i][6], acc[i][7]};
        *(float4*)&Y[row] = v0;
        *(float4*)&Y[row + 4] = v1;
    }
    // BN1 stats partials
    {
        float (*r0)[128] = As;
        float (*r1)[128] = Ws;
#pragma unroll
        for (int j = 0; j < 8; j++) {
            float s = 0.0f, q = 0.0f;
#pragma unroll
            for (int i = 0; i < 8; i++) { s += acc[i][j]; q += acc[i][j] * acc[i][j]; }
            r0[ty][tx * 8 + j] = s;
            r1[ty][tx * 8 + j] = q;
        }
        __syncthreads();
        if (tid < 128) {
            float S = 0.0f, Q = 0.0f;
#pragma unroll
            for (int i = 0; i < 16; i++) { S += r0[i][tid]; Q += r1[i][tid]; }
            size_t o = (size_t)blockIdx.x * C1 + tid;
            part[o] = S;
            part[PSQ_OFF + o] = Q;
        }
    }
}

// ============================================================================
// 3) GEMM2: fuseA (BN1+ReLU on input), group-max + BN2-stats epilogue, no Y.
//    128x128 tile, 256 threads, 8x8 register tile, A-register pipeline.
// ============================================================================
__global__ __launch_bounds__(256, 2)
void gemm2_kernel(const float* __restrict__ A, const float* __restrict__ W,
                  const float* __restrict__ bias,
                  const float* __restrict__ aScale, const float* __restrict__ aBias,
                  float* __restrict__ gmax, float* __restrict__ part) {
    const int K = 128;
    const int Nout = C2;
    __shared__ float As[16][128];
    __shared__ float Ws[16][128];
    int m0 = blockIdx.x * 128;
    int c0 = blockIdx.y * 128;
    int tid = threadIdx.x;
    int tx = tid & 15, ty = tid >> 4;
    int lrow = tid & 127, khalf = tid >> 7;
    int kb = khalf * 8;

    float acc[8][8];
#pragma unroll
    for (int i = 0; i < 8; i++)
#pragma unroll
        for (int j = 0; j < 8; j++) acc[i][j] = 0.0f;

    float ar[8];
    {
        const float* ap = &A[(size_t)(m0 + lrow) * K + kb];
        float4 a0 = *(const float4*)ap;
        float4 a1 = *(const float4*)(ap + 4);
        ar[0] = a0.x; ar[1] = a0.y; ar[2] = a0.z; ar[3] = a0.w;
        ar[4] = a1.x; ar[5] = a1.y; ar[6] = a1.z; ar[7] = a1.w;
    }

    for (int kt = 0; kt < 8; kt++) {
        int k0 = kt * 16;
#pragma unroll
        for (int u = 0; u < 8; u++) {
            float x = fmaxf(fmaf(ar[u], aScale[k0 + kb + u], aBias[k0 + kb + u]), 0.0f);
            As[kb + u][lrow] = x;
        }
        {
            const float* wp = &W[(size_t)(c0 + lrow) * K + k0 + kb];
            float4 w0 = *(const float4*)wp;
            float4 w1 = *(const float4*)(wp + 4);
            Ws[kb + 0][lrow] = w0.x; Ws[kb + 1][lrow] = w0.y;
            Ws[kb + 2][lrow] = w0.z; Ws[kb + 3][lrow] = w0.w;
            Ws[kb + 4][lrow] = w1.x; Ws[kb + 5][lrow] = w1.y;
            Ws[kb + 6][lrow] = w1.z; Ws[kb + 7][lrow] = w1.w;
        }
        __syncthreads();
        if (kt < 7) {
            const float* ap = &A[(size_t)(m0 + lrow) * K + k0 + 16 + kb];
            float4 a0 = *(const float4*)ap;
            float4 a1 = *(const float4*)(ap + 4);
            ar[0] = a0.x; ar[1] = a0.y; ar[2] = a0.z; ar[3] = a0.w;
            ar[4] = a1.x; ar[5] = a1.y; ar[6] = a1.z; ar[7] = a1.w;
        }
#pragma unroll
        for (int kk = 0; kk < 16; kk++) {
            float4 xa0 = *(const float4*)&As[kk][ty * 8];
            float4 xa1 = *(const float4*)&As[kk][ty * 8 + 4];
            float4 xb0 = *(const float4*)&Ws[kk][tx * 8];
            float4 xb1 = *(const float4*)&Ws[kk][tx * 8 + 4];
            float av[8] = {xa0.x, xa0.y, xa0.z, xa0.w, xa1.x, xa1.y, xa1.z, xa1.w};
            float bv[8] = {xb0.x, xb0.y, xb0.z, xb0.w, xb1.x, xb1.y, xb1.z, xb1.w};
#pragma unroll
            for (int i = 0; i < 8; i++)
#pragma unroll
                for (int j = 0; j < 8; j++) acc[i][j] += av[i] * bv[j];
        }
        __syncthreads();
    }
#pragma unroll
    for (int i = 0; i < 8; i++)
#pragma unroll
        for (int j = 0; j < 8; j++) acc[i][j] += bias[c0 + tx * 8 + j];

    // group-of-16 max epilogue
    {
        float (*redm)[128] = As;
#pragma unroll
        for (int j = 0; j < 8; j++) {
            float m = acc[0][j];
#pragma unroll
            for (int i = 1; i < 8; i++) m = fmaxf(m, acc[i][j]);
            redm[ty][tx * 8 + j] = m;
        }
        __syncthreads();
        if (ty < 8) {
#pragma unroll
            for (int j = 0; j < 8; j++) {
                int c = tx * 8 + j;
                float m = fmaxf(redm[2 * ty][c], redm[2 * ty + 1][c]);
                gmax[(size_t)(m0 / 16 + ty) * Nout + c0 + c] = m;
            }
        }
        __syncthreads();
    }
    // BN2 stats partials
    {
        float (*r0)[128] = As;
        float (*r1)[128] = Ws;
#pragma unroll
        for (int j = 0; j < 8; j++) {
            float s = 0.0f, q = 0.0f;
#pragma unroll
            for (int i = 0; i < 8; i++) { s += acc[i][j]; q += acc[i][j] * acc[i][j]; }
            r0[ty][tx * 8 + j] = s;
            r1[ty][tx * 8 + j] = q;
        }
        __syncthreads();
        if (tid < 128) {
            float S = 0.0f, Q = 0.0f;
#pragma unroll
            for (int i = 0; i < 16; i++) { S += r0[i][tid]; Q += r1[i][tid]; }
            size_t o = (size_t)blockIdx.x * Nout + c0 + tid;
            part[o] = S;
            part[PSQ_OFF + o] = Q;
        }
    }
}

// ============================================================================
// 4) BN stats reduction + finalize
// ============================================================================
__global__ void reduce_kernel(const float* __restrict__ part, float* __restrict__ red, int C) {
    int c = threadIdx.x;
    int r = blockIdx.x;
    float S = 0.0f, Q = 0.0f;
    for (int m = r * 32; m < r * 32 + 32; m++) {
        size_t o = (size_t)m * C + c;
        S += part[o];
        Q += part[PSQ_OFF + o];
    }
    red[r * C + c] = S;
    red[RSQ_OFF + r * C + c] = Q;
}

__global__ void finalize_kernel(const float* __restrict__ red,
                                const float* __restrict__ gamma,
                                const float* __restrict__ beta,
                                float* __restrict__ scale, float* __restrict__ bias, int C) {
    int c = threadIdx.x;
    float s = 0.0f, q = 0.0f;
    for (int r = 0; r < 32; r++) {
        s += red[r * C + c];
        q += red[RSQ_OFF + r * C + c];
    }
    const float inv = 1.0f / (float)MROWS;
    float m = s * inv;
    float v = q * inv - m * m;
    float sc = gamma[c] * rsqrtf(v + 1e-5f);
    scale[c] = sc;
    bias[c] = beta[c] - m * sc;
}

// ============================================================================
// 5) BN2 + ReLU on the pre-reduced group max (monotone: scale > 0).
// ============================================================================
__global__ __launch_bounds__(256, 4)
void maxpool_kernel(const float* __restrict__ gmax, const float* __restrict__ scale,
                    const float* __restrict__ bias, float* __restrict__ out) {
    int g = blockIdx.x;
    int c = threadIdx.x;
    float v = fmaf(gmax[(size_t)g * C2 + c], scale[c], bias[c]);
    out[(size_t)g * C2 + c] = fmaxf(v, 0.0f);
}

// ============================================================================
extern "C" void kernel_launch(void* const* d_in, const int* in_sizes, int n_in,
                              void* d_out, int out_size) {
    const float* xyz    = (const float*)d_in[0];
    const float* feat   = (const float*)d_in[1];
    const float* W1     = (const float*)d_in[2];
    const float* b1     = (const float*)d_in[3];
    const float* gamma1 = (const float*)d_in[4];
    const float* beta1  = (const float*)d_in[5];
    const float* W2     = (const float*)d_in[6];
    const float* b2     = (const float*)d_in[7];
    const float* gamma2 = (const float*)d_in[8];
    const float* beta2  = (const float*)d_in[9];

    float* out = (float*)d_out;
    float* out_newxyz = out;                            // [B,S,3]
    float* out_x      = out + (size_t)BATCH * SPT * 3;  // [B,S,C2]

    float *y1, *gmax, *part, *red, *scale, *bias;
    cudaGetSymbolAddress((void**)&y1,    g_y1);
    cudaGetSymbolAddress((void**)&gmax,  g_max);
    cudaGetSymbolAddress((void**)&part,  g_part);
    cudaGetSymbolAddress((void**)&red,   g_red);
    cudaGetSymbolAddress((void**)&scale, g_scale);
    cudaGetSymbolAddress((void**)&bias,  g_bias);

    // 0. SoA transpose of xyz (+ progress counter reset)
    soa_kernel<<<(BATCH * NPT) / 256, 256>>>(xyz);
    // 1. FPS (cluster kernel; writes new_xyz + progress; triggers PDL)
    cudaFuncSetAttribute(fps_cluster_kernel,
                         cudaFuncAttributeMaxDynamicSharedMemorySize, FPS_SMEM);
    fps_cluster_kernel<<<BATCH * FC, FT, FPS_SMEM>>>(out_newxyz);
    // 2. fused kNN + conv1, launched with PDL so it streams behind FPS
    {
        cudaLaunchConfig_t cfg = {};
        cfg.gridDim = dim3(MBLK, 1, 1);
        cfg.blockDim = dim3(256, 1, 1);
        cfg.dynamicSmemBytes = 0;
        cfg.stream = 0;
        cudaLaunchAttribute at[1];
        at[0].id = cudaLaunchAttributeProgrammaticStreamSerialization;
        at[0].val.programmaticStreamSerializationAllowed = 1;
        cfg.attrs = at;
        cfg.numAttrs = 1;
        cudaLaunchKernelEx(&cfg, fused_knn_gemm1,
                           (const float*)out_newxyz, feat, W1, b1, y1, part);
    }
    reduce_kernel<<<32, C1>>>(part, red, C1);
    finalize_kernel<<<1, C1>>>(red, gamma1, beta1, scale, bias, C1);
    // 3. conv2: fused BN1+ReLU input, group-max + BN2-stats epilogue
    {
        dim3 grid(MBLK, C2 / 128);
        gemm2_kernel<<<grid, 256>>>(y1, W2, b2, scale, bias, gmax, part);
    }
    reduce_kernel<<<32, C2>>>(part, red, C2);
    finalize_kernel<<<1, C2>>>(red, gamma2, beta2, scale, bias, C2);
    // 4. BN2+ReLU on pre-reduced max -> output
    maxpool_kernel<<<BATCH * SPT, C2>>>(gmax, scale, bias, out_x);
}

// round 14
// speedup vs baseline: 1.1653x; 1.1653x over previous
#include <cuda_runtime.h>
#include <cuda_bf16.h>
#include <cstdint>
#include <float.h>

// Problem constants (shapes fixed by the dataset)
#define BATCH 4
#define NPT   16384
#define SPT   2048
#define KNN   16
#define DFEAT 125
#define C0    128
#define C1    128
#define C2    256
#define MROWS (BATCH * SPT * KNN)   // 131072 samples through the MLP
#define MBLK  (MROWS / 128)         // 1024 gemm m-blocks (128-row tiles)
#define PSQ_OFF (MBLK * 256)        // sumsq offset inside g_part
#define RSQ_OFF (32 * 256)          // sumsq offset inside g_red

// FPS cluster config: 8 CTAs x 256 threads per batch
#define FC 8
#define FT 256
#define FP (NPT / FC / FT)          // 8 points per thread
#define XT (FC * 8)                 // tx bytes per exchange (8 sources x 8B)
#define FPS_SMEM (3 * NPT * 4)      // full batch xyz in SMEM (192 KB)

// fused kernel: oversized dynamic smem EXCLUDES co-residency with FPS
// (192KB + 100KB > 228KB/SM) while allowing 2 CTAs on free SMs.
#define FUSED_SMEM (100 * 1024)

// ---------------- scratch (static device globals; no allocation allowed) ----
__device__ float g_y1[(size_t)MROWS * C1];     // conv1 out (raw, pre-BN)
__device__ float g_max[(size_t)BATCH * SPT * C2]; // raw per-group max (8.4MB)
__device__ float g_part[2 * MBLK * 256];       // per-mblock [sum | sumsq]
__device__ float g_red[2 * 32 * 256];          // stage-1 reduced partials
__device__ float g_scale[256];
__device__ float g_bias[256];
__device__ int   g_prog[BATCH];                // FPS progress (samples done)
__device__ float g_sx[BATCH * NPT];            // SoA xyz
__device__ float g_sy[BATCH * NPT];
__device__ float g_sz[BATCH * NPT];

// ---------------------------------------------------------------------------
// helpers
// ---------------------------------------------------------------------------
__device__ __forceinline__ uint32_t smem_u32(const void* p) {
    return (uint32_t)__cvta_generic_to_shared(p);
}
__device__ __forceinline__ uint32_t mapa_u32(uint32_t addr, uint32_t rank) {
    uint32_t r;
    asm("mapa.shared::cluster.u32 %0, %1, %2;" : "=r"(r) : "r"(addr), "r"(rank));
    return r;
}
__device__ __forceinline__ void st_async_u64(uint32_t raddr, uint32_t rmbar, uint64_t v) {
    asm volatile("st.async.shared::cluster.mbarrier::complete_tx::bytes.b64 [%0], %1, [%2];"
                 :: "r"(raddr), "l"(v), "r"(rmbar) : "memory");
}
__device__ __forceinline__ void mbar_inval(uint32_t a) {
    asm volatile("mbarrier.inval.shared.b64 [%0];" :: "r"(a) : "memory");
}
__device__ __forceinline__ void mbar_init(uint32_t a, uint32_t cnt) {
    asm volatile("mbarrier.init.shared.b64 [%0], %1;" :: "r"(a), "r"(cnt) : "memory");
}
__device__ __forceinline__ void mbar_arrive_expect(uint32_t a, uint32_t tx) {
    asm volatile("mbarrier.arrive.expect_tx.shared.b64 _, [%0], %1;"
                 :: "r"(a), "r"(tx) : "memory");
}
__device__ __forceinline__ void mbar_wait(uint32_t mbar, uint32_t parity) {
    asm volatile(
        "{\n\t.reg .pred P;\n\t"
        "WAIT_%=:\n\t"
        "mbarrier.try_wait.parity.acquire.cluster.shared::cta.b64 P, [%0], %1, 0x989680;\n\t"
        "@P bra.uni DONE_%=;\n\t"
        "bra.uni WAIT_%=;\n\t"
        "DONE_%=:\n\t}"
        :: "r"(mbar), "r"(parity) : "memory");
}
__device__ __forceinline__ uint64_t u64max(uint64_t a, uint64_t b) {
    return (a > b) ? a : b;
}
__device__ __forceinline__ void st_rel_i32(int* p, int v) {
    asm volatile("st.release.gpu.global.s32 [%0], %1;" :: "l"(p), "r"(v) : "memory");
}
__device__ __forceinline__ int ld_acq_i32(const int* p) {
    int v;
    asm volatile("ld.acquire.gpu.global.s32 %0, [%1];" : "=r"(v) : "l"(p) : "memory");
    return v;
}
// L2-coherent load (bypass L1) — required for data produced by a
// CONCURRENTLY RUNNING kernel (plain ld.global can hit stale L1 lines).
__device__ __forceinline__ float ld_cg_f32(const float* p) {
    float v;
    asm volatile("ld.global.cg.f32 %0, [%1];" : "=f"(v) : "l"(p) : "memory");
    return v;
}

// ============================================================================
// 0) AoS -> SoA transpose of xyz (coalesced via smem staging) + zero progress
// ============================================================================
__global__ __launch_bounds__(256)
void soa_kernel(const float* __restrict__ xyz) {
    __shared__ float buf[768];
    int t = threadIdx.x;
    if (blockIdx.x == 0 && t < BATCH) g_prog[t] = 0;
    size_t base = (size_t)blockIdx.x * 768;
#pragma unroll
    for (int r = 0; r < 3; r++) buf[t + 256 * r] = xyz[base + t + 256 * r];
    __syncthreads();
    size_t o = (size_t)blockIdx.x * 256 + t;
    g_sx[o] = buf[t * 3 + 0];
    g_sy[o] = buf[t * 3 + 1];
    g_sz[o] = buf[t * 3 + 2];
}

// ============================================================================
// 1) FPS (R10 protocol) + progress publication + PDL trigger.
// ============================================================================
__global__ __launch_bounds__(FT, 1) __cluster_dims__(FC, 1, 1)
void fps_cluster_kernel(float* __restrict__ new_xyz) {
    extern __shared__ float smem[];
    float* shx = smem;
    float* shy = smem + NPT;
    float* shz = smem + 2 * NPT;

    int b = blockIdx.x / FC;
    int rank = blockIdx.x % FC;
    int t = threadIdx.x;
    int w = t >> 5, lane = t & 31;
    int base = rank * (NPT / FC);
    const float* sx = g_sx + (size_t)b * NPT;
    const float* sy = g_sy + (size_t)b * NPT;
    const float* sz = g_sz + (size_t)b * NPT;

    for (int i = t; i < NPT; i += FT) {
        shx[i] = sx[i]; shy[i] = sy[i]; shz[i] = sz[i];
    }

    float px[FP], py[FP], pz[FP], dist[FP];
#pragma unroll
    for (int j = 0; j < FP; j++) {
        int i = base + j * FT + t;
        px[j] = sx[i]; py[j] = sy[i]; pz[j] = sz[i];
        dist[j] = 1e10f;
    }

    __shared__ __align__(8) uint64_t c_slot[2][FC];
    __shared__ __align__(8) uint64_t mbar[2];
    __shared__ __align__(8) uint64_t s_key[8];

    uint32_t mb0 = smem_u32(&mbar[0]);
    uint32_t mb1 = smem_u32(&mbar[1]);

    if (t == 0) {
        mbar_inval(mb0); mbar_inval(mb1);
        mbar_init(mb0, 1); mbar_init(mb1, 1);
        mbar_arrive_expect(mb0, 0);
        mbar_arrive_expect(mb0, XT);
        mbar_arrive_expect(mb1, XT);
    }
    __syncthreads();
    asm volatile("barrier.cluster.arrive.aligned;" ::: "memory");
    asm volatile("barrier.cluster.wait.aligned;" ::: "memory");

    // all FPS CTAs are resident now -> allow the fused kernel to dispatch
    if (t == 0) cudaTriggerProgrammaticLaunchCompletion();

    uint32_t r_s0 = 0, r_s1 = 0, r_m0 = 0, r_m1 = 0;
    if (w == 0 && lane < FC) {
        r_s0 = mapa_u32(smem_u32(&c_slot[0][rank]), lane);
        r_s1 = mapa_u32(smem_u32(&c_slot[1][rank]), lane);
        r_m0 = mapa_u32(mb0, lane);
        r_m1 = mapa_u32(mb1, lane);
    }

    float curx = shx[0], cury = shy[0], curz = shz[0];
    float* out = new_xyz + (size_t)b * SPT * 3;

    for (int s = 0; s < SPT; s++) {
        if (s > 0) {
            uint32_t mb = (s & 1) ? mb1 : mb0;
            mbar_wait(mb, (unsigned)((s >> 1) & 1));
            int bf = s & 1;
            uint64_t k0 = c_slot[bf][0], k1 = c_slot[bf][1];
            uint64_t k2 = c_slot[bf][2], k3 = c_slot[bf][3];
            uint64_t k4 = c_slot[bf][4], k5 = c_slot[bf][5];
            uint64_t k6 = c_slot[bf][6], k7 = c_slot[bf][7];
            uint64_t wk = u64max(u64max(u64max(k0, k1), u64max(k2, k3)),
                                 u64max(u64max(k4, k5), u64max(k6, k7)));
            int wi = (int)(~(uint32_t)wk);
            curx = shx[wi]; cury = shy[wi]; curz = shz[wi];
        }
        if (rank == 0 && t == 0) {
            out[s * 3 + 0] = curx;
            out[s * 3 + 1] = cury;
            out[s * 3 + 2] = curz;
            st_rel_i32(&g_prog[b], s + 1);   // publish sample s
        }
        float best = -1.0f; int bj = 0;
#pragma unroll
        for (int j = 0; j < FP; j++) {
            float dx = px[j] - curx, dy = py[j] - cury, dz = pz[j] - curz;
            float d = __fadd_rn(__fadd_rn(__fmul_rn(dx, dx), __fmul_rn(dy, dy)),
                                __fmul_rn(dz, dz));
            float nd = fminf(dist[j], d);
            dist[j] = nd;
            bool bt = nd > best;
            best = bt ? nd : best;
            bj = bt ? j : bj;
        }
        unsigned bi = (unsigned)(base + bj * FT + t);
        unsigned vb = __float_as_uint(best);
        unsigned mv = __reduce_max_sync(0xffffffffu, vb);
        unsigned cnd = (vb == mv) ? ~bi : 0u;
        unsigned ml = __reduce_max_sync(0xffffffffu, cnd);
        if (lane == 0) s_key[w] = ((uint64_t)mv << 32) | ml;
        __syncthreads();
        if (w == 0) {
            if (s + 1 < SPT) {
                unsigned hi = (lane < 8) ? (unsigned)(s_key[lane] >> 32) : 0u;
                unsigned lo = (lane < 8) ? (unsigned)s_key[lane] : 0u;
                unsigned mv2 = __reduce_max_sync(0xffffffffu, hi);
                unsigned c2 = (hi == mv2) ? lo : 0u;
                unsigned ml2 = __reduce_max_sync(0xffffffffu, c2);
                if (lane < FC) {
                    int st = (s + 1) & 1;
                    uint32_t rs = st ? r_s1 : r_s0;
                    uint32_t rm = st ? r_m1 : r_m0;
                    st_async_u64(rs, rm, ((uint64_t)mv2 << 32) | ml2);
                }
            }
            if (lane == 8 && s > 0 && s + 2 < SPT)
                mbar_arrive_expect((s & 1) ? mb1 : mb0, XT);
        }
    }
    asm volatile("barrier.cluster.arrive.aligned;" ::: "memory");
    asm volatile("barrier.cluster.wait.aligned;" ::: "memory");
}

// ============================================================================
// 2) FUSED kNN + conv1 (PDL secondary; streams behind FPS).
//    Changes vs R13 (which slowed FPS by ~2x):
//    - 100KB dynamic smem so fused CTAs can NEVER co-reside with FPS CTAs
//      (192+100 > 228KB/SM) -> no issue-slot stealing on the critical SMs.
//    - ONE poller per CTA (tid 0, waits for the block's LAST query; progress
//      is monotone so all 8 are then ready) with 1us backoff -> ~64x less
//      load traffic on g_prog's L2 slice (R13's poll storm queued ahead of
//      FPS's release store).
//    All newxyz reads are ld.global.cg (concurrent-producer coherence).
// ============================================================================
__global__ __launch_bounds__(256)
void fused_knn_gemm1(const float* __restrict__ newxyz, const float* __restrict__ feat,
                     const float* __restrict__ W, const float* __restrict__ bias,
                     float* __restrict__ Y, float* __restrict__ part) {
    const int K = 128;
    extern __shared__ float fsm[];
    float (*As)[128] = (float (*)[128])fsm;              // 16x128
    float (*Ws)[128] = (float (*)[128])(fsm + 2048);     // 16x128
    int* s_idx = (int*)(fsm + 4096);                     // 128 ints
    int tid = threadIdx.x;
    int w = tid >> 5, lane = tid & 31;
    int m0 = blockIdx.x * 128;

    // ---- wait: one poller for the whole block ----
    {
        int glast = blockIdx.x * 8 + 7;
        int b = glast >> 11;
        int q = glast & 2047;
        if (tid == 0) {
            while (ld_acq_i32(&g_prog[b]) < q + 1) __nanosleep(1024);
        }
        __syncthreads();
    }

    // ---- Phase A: kNN for this block's 8 queries (one per warp) ----
    {
        int g = blockIdx.x * 8 + w;
        int b = g >> 11;
        const float* sx = g_sx + (size_t)b * NPT;
        const float* sy = g_sy + (size_t)b * NPT;
        const float* sz = g_sz + (size_t)b * NPT;
        float qx = ld_cg_f32(&newxyz[(size_t)g * 3 + 0]);
        float qy = ld_cg_f32(&newxyz[(size_t)g * 3 + 1]);
        float qz = ld_cg_f32(&newxyz[(size_t)g * 3 + 2]);

        float tv = (lane < 16) ? FLT_MAX : 0.0f;
        int   tix = 0;
        float ww = FLT_MAX;
        for (int i = 0; i < NPT / 32; i++) {
            int base = i << 5;
            float dx = sx[base + lane] - qx;
            float dy = sy[base + lane] - qy;
            float dz = sz[base + lane] - qz;
            float d = dx * dx + dy * dy + dz * dz;
            unsigned m = __ballot_sync(0xffffffffu, d < ww);
            while (m) {
                int src = __ffs(m) - 1; m &= m - 1;
                float dc = __shfl_sync(0xffffffffu, d, src);
                if (dc < ww) {
                    unsigned mv = __reduce_max_sync(0xffffffffu, __float_as_uint(tv));
                    unsigned own = __ballot_sync(0xffffffffu, __float_as_uint(tv) == mv) & 0xffffu;
                    if (lane == __ffs(own) - 1) { tv = dc; tix = base + src; }
                    ww = __uint_as_float(__reduce_max_sync(0xffffffffu, __float_as_uint(tv)));
                }
            }
        }
        if (lane < 16) s_idx[w * 16 + lane] = tix;
    }
    __syncthreads();

    // ---- Phase B: gemm1 for rows [m0, m0+128), gather from s_idx ----
    int tx = tid & 15, ty = tid >> 4;
    int lrow = tid & 127, khalf = tid >> 7;
    int kb = khalf * 8;

    const float* gfp;
    float gx0 = 0.0f, gx1 = 0.0f, gx2 = 0.0f;
    {
        int n = m0 + lrow;
        int g = n >> 4;
        int bb = g >> 11;
        int idx = s_idx[lrow];
        size_t p = (size_t)bb * NPT + idx;
        gfp = feat + p * DFEAT;
        if (khalf == 0) {
            gx0 = g_sx[p] - ld_cg_f32(&newxyz[(size_t)g * 3 + 0]);
            gx1 = g_sy[p] - ld_cg_f32(&newxyz[(size_t)g * 3 + 1]);
            gx2 = g_sz[p] - ld_cg_f32(&newxyz[(size_t)g * 3 + 2]);
        }
    }

    float acc[8][8];
#pragma unroll
    for (int i = 0; i < 8; i++)
#pragma unroll
        for (int j = 0; j < 8; j++) acc[i][j] = 0.0f;

    float ar[8];
#pragma unroll
    for (int u = 0; u < 8; u++) {
        int cc = kb + u - 3;
        ar[u] = gfp[cc < 0 ? 0 : cc];
    }
    if (khalf == 0) { ar[0] = gx0; ar[1] = gx1; ar[2] = gx2; }

    for (int kt = 0; kt < 8; kt++) {
        int k0 = kt * 16;
#pragma unroll
        for (int u = 0; u < 8; u++) As[kb + u][lrow] = ar[u];
        {
            const float* wp = &W[(size_t)lrow * K + k0 + kb];
            float4 w0 = *(const float4*)wp;
            float4 w1 = *(const float4*)(wp + 4);
            Ws[kb + 0][lrow] = w0.x; Ws[kb + 1][lrow] = w0.y;
            Ws[kb + 2][lrow] = w0.z; Ws[kb + 3][lrow] = w0.w;
            Ws[kb + 4][lrow] = w1.x; Ws[kb + 5][lrow] = w1.y;
            Ws[kb + 6][lrow] = w1.z; Ws[kb + 7][lrow] = w1.w;
        }
        __syncthreads();
        if (kt < 7) {
            int kn = k0 + 16;
#pragma unroll
            for (int u = 0; u < 8; u++) ar[u] = gfp[kn + kb + u - 3];
        }
#pragma unroll
        for (int kk = 0; kk < 16; kk++) {
            float4 xa0 = *(const float4*)&As[kk][ty * 8];
            float4 xa1 = *(const float4*)&As[kk][ty * 8 + 4];
            float4 xb0 = *(const float4*)&Ws[kk][tx * 8];
            float4 xb1 = *(const float4*)&Ws[kk][tx * 8 + 4];
            float av[8] = {xa0.x, xa0.y, xa0.z, xa0.w, xa1.x, xa1.y, xa1.z, xa1.w};
            float bv[8] = {xb0.x, xb0.y, xb0.z, xb0.w, xb1.x, xb1.y, xb1.z, xb1.w};
#pragma unroll
            for (int i = 0; i < 8; i++)
#pragma unroll
                for (int j = 0; j < 8; j++) acc[i][j] += av[i] * bv[j];
        }
        __syncthreads();
    }
#pragma unroll
    for (int i = 0; i < 8; i++)
#pragma unroll
        for (int j = 0; j < 8; j++) acc[i][j] += bias[tx * 8 + j];

#pragma unroll
    for (int i = 0; i < 8; i++) {
        size_t row = (size_t)(m0 + ty * 8 + i) * C1 + tx * 8;
        float4 v0 = {acc[i][0], acc[i][1], acc[i][2], acc[i][3]};
        float4 v1 = {acc[i][4], acc[i][5], acc[i][6], acc[i][7]};
        *(float4*)&Y[row] = v0;
        *(float4*)&Y[row + 4] = v1;
    }
    // BN1 stats partials
    {
        float (*r0)[128] = As;
        float (*r1)[128] = Ws;
#pragma unroll
        for (int j = 0; j < 8; j++) {
            float s = 0.0f, q = 0.0f;
#pragma unroll
            for (int i = 0; i < 8; i++) { s += acc[i][j]; q += acc[i][j] * acc[i][j]; }
            r0[ty][tx * 8 + j] = s;
            r1[ty][tx * 8 + j] = q;
        }
        __syncthreads();
        if (tid < 128) {
            float S = 0.0f, Q = 0.0f;
#pragma unroll
            for (int i = 0; i < 16; i++) { S += r0[i][tid]; Q += r1[i][tid]; }
            size_t o = (size_t)blockIdx.x * C1 + tid;
            part[o] = S;
            part[PSQ_OFF + o] = Q;
        }
    }
}

// ============================================================================
// 3) GEMM2: fuseA (BN1+ReLU on input), group-max + BN2-stats epilogue, no Y.
// ============================================================================
__global__ __launch_bounds__(256, 2)
void gemm2_kernel(const float* __restrict__ A, const float* __restrict__ W,
                  const float* __restrict__ bias,
                  const float* __restrict__ aScale, const float* __restrict__ aBias,
                  float* __restrict__ gmax, float* __restrict__ part) {
    const int K = 128;
    const int Nout = C2;
    __shared__ float As[16][128];
    __shared__ float Ws[16][128];
    int m0 = blockIdx.x * 128;
    int c0 = blockIdx.y * 128;
    int tid = threadIdx.x;
    int tx = tid & 15, ty = tid >> 4;
    int lrow = tid & 127, khalf = tid >> 7;
    int kb = khalf * 8;

    float acc[8][8];
#pragma unroll
    for (int i = 0; i < 8; i++)
#pragma unroll
        for (int j = 0; j < 8; j++) acc[i][j] = 0.0f;

    float ar[8];
    {
        const float* ap = &A[(size_t)(m0 + lrow) * K + kb];
        float4 a0 = *(const float4*)ap;
        float4 a1 = *(const float4*)(ap + 4);
        ar[0] = a0.x; ar[1] = a0.y; ar[2] = a0.z; ar[3] = a0.w;
        ar[4] = a1.x; ar[5] = a1.y; ar[6] = a1.z; ar[7] = a1.w;
    }

    for (int kt = 0; kt < 8; kt++) {
        int k0 = kt * 16;
#pragma unroll
        for (int u = 0; u < 8; u++) {
            float x = fmaxf(fmaf(ar[u], aScale[k0 + kb + u], aBias[k0 + kb + u]), 0.0f);
            As[kb + u][lrow] = x;
        }
        {
            const float* wp = &W[(size_t)(c0 + lrow) * K + k0 + kb];
            float4 w0 = *(const float4*)wp;
            float4 w1 = *(const float4*)(wp + 4);
            Ws[kb + 0][lrow] = w0.x; Ws[kb + 1][lrow] = w0.y;
            Ws[kb + 2][lrow] = w0.z; Ws[kb + 3][lrow] = w0.w;
            Ws[kb + 4][lrow] = w1.x; Ws[kb + 5][lrow] = w1.y;
            Ws[kb + 6][lrow] = w1.z; Ws[kb + 7][lrow] = w1.w;
        }
        __syncthreads();
        if (kt < 7) {
            const float* ap = &A[(size_t)(m0 + lrow) * K + k0 + 16 + kb];
            float4 a0 = *(const float4*)ap;
            float4 a1 = *(const float4*)(ap + 4);
            ar[0] = a0.x; ar[1] = a0.y; ar[2] = a0.z; ar[3] = a0.w;
            ar[4] = a1.x; ar[5] = a1.y; ar[6] = a1.z; ar[7] = a1.w;
        }
#pragma unroll
        for (int kk = 0; kk < 16; kk++) {
            float4 xa0 = *(const float4*)&As[kk][ty * 8];
            float4 xa1 = *(const float4*)&As[kk][ty * 8 + 4];
            float4 xb0 = *(const float4*)&Ws[kk][tx * 8];
            float4 xb1 = *(const float4*)&Ws[kk][tx * 8 + 4];
            float av[8] = {xa0.x, xa0.y, xa0.z, xa0.w, xa1.x, xa1.y, xa1.z, xa1.w};
            float bv[8] = {xb0.x, xb0.y, xb0.z, xb0.w, xb1.x, xb1.y, xb1.z, xb1.w};
#pragma unroll
            for (int i = 0; i < 8; i++)
#pragma unroll
                for (int j = 0; j < 8; j++) acc[i][j] += av[i] * bv[j];
        }
        __syncthreads();
    }
#pragma unroll
    for (int i = 0; i < 8; i++)
#pragma unroll
        for (int j = 0; j < 8; j++) acc[i][j] += bias[c0 + tx * 8 + j];

    // group-of-16 max epilogue
    {
        float (*redm)[128] = As;
#pragma unroll
        for (int j = 0; j < 8; j++) {
            float m = acc[0][j];
#pragma unroll
            for (int i = 1; i < 8; i++) m = fmaxf(m, acc[i][j]);
            redm[ty][tx * 8 + j] = m;
        }
        __syncthreads();
        if (ty < 8) {
#pragma unroll
            for (int j = 0; j < 8; j++) {
                int c = tx * 8 + j;
                float m = fmaxf(redm[2 * ty][c], redm[2 * ty + 1][c]);
                gmax[(size_t)(m0 / 16 + ty) * Nout + c0 + c] = m;
            }
        }
        __syncthreads();
    }
    // BN2 stats partials
    {
        float (*r0)[128] = As;
        float (*r1)[128] = Ws;
#pragma unroll
        for (int j = 0; j < 8; j++) {
            float s = 0.0f, q = 0.0f;
#pragma unroll
            for (int i = 0; i < 8; i++) { s += acc[i][j]; q += acc[i][j] * acc[i][j]; }
            r0[ty][tx * 8 + j] = s;
            r1[ty][tx * 8 + j] = q;
        }
        __syncthreads();
        if (tid < 128) {
            float S = 0.0f, Q = 0.0f;
#pragma unroll
            for (int i = 0; i < 16; i++) { S += r0[i][tid]; Q += r1[i][tid]; }
            size_t o = (size_t)blockIdx.x * Nout + c0 + tid;
            part[o] = S;
            part[PSQ_OFF + o] = Q;
        }
    }
}

// ============================================================================
// 4) BN stats reduction + finalize
// ============================================================================
__global__ void reduce_kernel(const float* __restrict__ part, float* __restrict__ red, int C) {
    int c = threadIdx.x;
    int r = blockIdx.x;
    float S = 0.0f, Q = 0.0f;
    for (int m = r * 32; m < r * 32 + 32; m++) {
        size_t o = (size_t)m * C + c;
        S += part[o];
        Q += part[PSQ_OFF + o];
    }
    red[r * C + c] = S;
    red[RSQ_OFF + r * C + c] = Q;
}

__global__ void finalize_kernel(const float* __restrict__ red,
                                const float* __restrict__ gamma,
                                const float* __restrict__ beta,
                                float* __restrict__ scale, float* __restrict__ bias, int C) {
    int c = threadIdx.x;
    float s = 0.0f, q = 0.0f;
    for (int r = 0; r < 32; r++) {
        s += red[r * C + c];
        q += red[RSQ_OFF + r * C + c];
    }
    const float inv = 1.0f / (float)MROWS;
    float m = s * inv;
    float v = q * inv - m * m;
    float sc = gamma[c] * rsqrtf(v + 1e-5f);
    scale[c] = sc;
    bias[c] = beta[c] - m * sc;
}

// ============================================================================
// 5) BN2 + ReLU on the pre-reduced group max (monotone: scale > 0).
// ============================================================================
__global__ __launch_bounds__(256, 4)
void maxpool_kernel(const float* __restrict__ gmax, const float* __restrict__ scale,
                    const float* __restrict__ bias, float* __restrict__ out) {
    int g = blockIdx.x;
    int c = threadIdx.x;
    float v = fmaf(gmax[(size_t)g * C2 + c], scale[c], bias[c]);
    out[(size_t)g * C2 + c] = fmaxf(v, 0.0f);
}

// ============================================================================
extern "C" void kernel_launch(void* const* d_in, const int* in_sizes, int n_in,
                              void* d_out, int out_size) {
    const float* xyz    = (const float*)d_in[0];
    const float* feat   = (const float*)d_in[1];
    const float* W1     = (const float*)d_in[2];
    const float* b1     = (const float*)d_in[3];
    const float* gamma1 = (const float*)d_in[4];
    const float* beta1  = (const float*)d_in[5];
    const float* W2     = (const float*)d_in[6];
    const float* b2     = (const float*)d_in[7];
    const float* gamma2 = (const float*)d_in[8];
    const float* beta2  = (const float*)d_in[9];

    float* out = (float*)d_out;
    float* out_newxyz = out;                            // [B,S,3]
    float* out_x      = out + (size_t)BATCH * SPT * 3;  // [B,S,C2]

    float *y1, *gmax, *part, *red, *scale, *bias;
    cudaGetSymbolAddress((void**)&y1,    g_y1);
    cudaGetSymbolAddress((void**)&gmax,  g_max);
    cudaGetSymbolAddress((void**)&part,  g_part);
    cudaGetSymbolAddress((void**)&red,   g_red);
    cudaGetSymbolAddress((void**)&scale, g_scale);
    cudaGetSymbolAddress((void**)&bias,  g_bias);

    // 0. SoA transpose of xyz (+ progress counter reset)
    soa_kernel<<<(BATCH * NPT) / 256, 256>>>(xyz);
    // 1. FPS (cluster kernel; writes new_xyz + progress; triggers PDL)
    cudaFuncSetAttribute(fps_cluster_kernel,
                         cudaFuncAttributeMaxDynamicSharedMemorySize, FPS_SMEM);
    fps_cluster_kernel<<<BATCH * FC, FT, FPS_SMEM>>>(out_newxyz);
    // 2. fused kNN + conv1, PDL, with smem sized to exclude FPS-SM residency
    {
        cudaFuncSetAttribute(fused_knn_gemm1,
                             cudaFuncAttributeMaxDynamicSharedMemorySize, FUSED_SMEM);
        cudaLaunchConfig_t cfg = {};
        cfg.gridDim = dim3(MBLK, 1, 1);
        cfg.blockDim = dim3(256, 1, 1);
        cfg.dynamicSmemBytes = FUSED_SMEM;
        cfg.stream = 0;
        cudaLaunchAttribute at[1];
        at[0].id = cudaLaunchAttributeProgrammaticStreamSerialization;
        at[0].val.programmaticStreamSerializationAllowed = 1;
        cfg.attrs = at;
        cfg.numAttrs = 1;
        cudaLaunchKernelEx(&cfg, fused_knn_gemm1,
                           (const float*)out_newxyz, feat, W1, b1, y1, part);
    }
    reduce_kernel<<<32, C1>>>(part, red, C1);
    finalize_kernel<<<1, C1>>>(red, gamma1, beta1, scale, bias, C1);
    // 3. conv2: fused BN1+ReLU input, group-max + BN2-stats epilogue
    {
        dim3 grid(MBLK, C2 / 128);
        gemm2_kernel<<<grid, 256>>>(y1, W2, b2, scale, bias, gmax, part);
    }
    reduce_kernel<<<32, C2>>>(part, red, C2);
    finalize_kernel<<<1, C2>>>(red, gamma2, beta2, scale, bias, C2);
    // 4. BN2+ReLU on pre-reduced max -> output
    maxpool_kernel<<<BATCH * SPT, C2>>>(gmax, scale, bias, out_x);
}

// round 15
// speedup vs baseline: 1.3683x; 1.1742x over previous
#include <cuda_runtime.h>
#include <cuda_bf16.h>
#include <cstdint>
#include <float.h>

// Problem constants (shapes fixed by the dataset)
#define BATCH 4
#define NPT   16384
#define SPT   2048
#define KNN   16
#define DFEAT 125
#define C0    128
#define C1    128
#define C2    256
#define MROWS (BATCH * SPT * KNN)   // 131072 samples through the MLP
#define MBLK  (MROWS / 128)         // 1024 gemm m-blocks (128-row tiles)
#define PSQ_OFF (MBLK * 256)        // sumsq offset inside g_part
#define RSQ_OFF (32 * 256)          // sumsq offset inside g_red

// FPS cluster config: 8 CTAs x 256 threads per batch
#define FC 8
#define FT 256
#define FP (NPT / FC / FT)          // 8 points per thread
#define XT (FC * 8)                 // tx bytes per exchange (8 sources x 8B)
#define FPS_SMEM (3 * NPT * 4)      // full batch xyz in SMEM (192 KB)

// ---------------- scratch (static device globals; no allocation allowed) ----
__device__ float g_y1[(size_t)MROWS * C1];     // conv1 out (raw, pre-BN)
__device__ float g_max[(size_t)BATCH * SPT * C2]; // raw per-group max (8.4MB)
__device__ float g_part[2 * MBLK * 256];       // per-mblock [sum | sumsq]
__device__ float g_red[2 * 32 * 256];          // stage-1 reduced partials
__device__ float g_scale[256];
__device__ float g_bias[256];
__device__ float g_sx[BATCH * NPT];            // SoA xyz
__device__ float g_sy[BATCH * NPT];
__device__ float g_sz[BATCH * NPT];

// ---------------------------------------------------------------------------
// helpers
// ---------------------------------------------------------------------------
__device__ __forceinline__ uint32_t smem_u32(const void* p) {
    return (uint32_t)__cvta_generic_to_shared(p);
}
__device__ __forceinline__ uint32_t mapa_u32(uint32_t addr, uint32_t rank) {
    uint32_t r;
    asm("mapa.shared::cluster.u32 %0, %1, %2;" : "=r"(r) : "r"(addr), "r"(rank));
    return r;
}
__device__ __forceinline__ void st_async_u64(uint32_t raddr, uint32_t rmbar, uint64_t v) {
    asm volatile("st.async.shared::cluster.mbarrier::complete_tx::bytes.b64 [%0], %1, [%2];"
                 :: "r"(raddr), "l"(v), "r"(rmbar) : "memory");
}
__device__ __forceinline__ void mbar_inval(uint32_t a) {
    asm volatile("mbarrier.inval.shared.b64 [%0];" :: "r"(a) : "memory");
}
__device__ __forceinline__ void mbar_init(uint32_t a, uint32_t cnt) {
    asm volatile("mbarrier.init.shared.b64 [%0], %1;" :: "r"(a), "r"(cnt) : "memory");
}
__device__ __forceinline__ void mbar_arrive_expect(uint32_t a, uint32_t tx) {
    asm volatile("mbarrier.arrive.expect_tx.shared.b64 _, [%0], %1;"
                 :: "r"(a), "r"(tx) : "memory");
}
__device__ __forceinline__ void mbar_wait(uint32_t mbar, uint32_t parity) {
    asm volatile(
        "{\n\t.reg .pred P;\n\t"
        "WAIT_%=:\n\t"
        "mbarrier.try_wait.parity.acquire.cluster.shared::cta.b64 P, [%0], %1, 0x989680;\n\t"
        "@P bra.uni DONE_%=;\n\t"
        "bra.uni WAIT_%=;\n\t"
        "DONE_%=:\n\t}"
        :: "r"(mbar), "r"(parity) : "memory");
}
__device__ __forceinline__ uint64_t u64max(uint64_t a, uint64_t b) {
    return (a > b) ? a : b;
}

// ============================================================================
// 0) AoS -> SoA transpose of xyz (coalesced via smem staging)
// ============================================================================
__global__ __launch_bounds__(256)
void soa_kernel(const float* __restrict__ xyz) {
    __shared__ float buf[768];
    int t = threadIdx.x;
    size_t base = (size_t)blockIdx.x * 768;
#pragma unroll
    for (int r = 0; r < 3; r++) buf[t + 256 * r] = xyz[base + t + 256 * r];
    __syncthreads();
    size_t o = (size_t)blockIdx.x * 256 + t;
    g_sx[o] = buf[t * 3 + 0];
    g_sy[o] = buf[t * 3 + 1];
    g_sz[o] = buf[t * 3 + 2];
}

// ============================================================================
// 1) FPS (R10/R11 protocol — best measured variant).
//    8-CTA x 256-thread cluster per batch; u64 key = (dist_bits<<32) | ~idx,
//    u64 max == jnp argmax tie-break; mbarrier + st.async exchange; batch
//    xyz SMEM-resident. Exact jnp semantics (no FMA contraction; sample 0 =
//    point 0; emits previous winner).
// ============================================================================
__global__ __launch_bounds__(FT, 1) __cluster_dims__(FC, 1, 1)
void fps_cluster_kernel(float* __restrict__ new_xyz) {
    extern __shared__ float smem[];
    float* shx = smem;
    float* shy = smem + NPT;
    float* shz = smem + 2 * NPT;

    int b = blockIdx.x / FC;
    int rank = blockIdx.x % FC;
    int t = threadIdx.x;
    int w = t >> 5, lane = t & 31;
    int base = rank * (NPT / FC);
    const float* sx = g_sx + (size_t)b * NPT;
    const float* sy = g_sy + (size_t)b * NPT;
    const float* sz = g_sz + (size_t)b * NPT;

    for (int i = t; i < NPT; i += FT) {
        shx[i] = sx[i]; shy[i] = sy[i]; shz[i] = sz[i];
    }

    float px[FP], py[FP], pz[FP], dist[FP];
#pragma unroll
    for (int j = 0; j < FP; j++) {
        int i = base + j * FT + t;
        px[j] = sx[i]; py[j] = sy[i]; pz[j] = sz[i];
        dist[j] = 1e10f;
    }

    __shared__ __align__(8) uint64_t c_slot[2][FC];
    __shared__ __align__(8) uint64_t mbar[2];
    __shared__ __align__(8) uint64_t s_key[8];

    uint32_t mb0 = smem_u32(&mbar[0]);
    uint32_t mb1 = smem_u32(&mbar[1]);

    if (t == 0) {
        mbar_inval(mb0); mbar_inval(mb1);
        mbar_init(mb0, 1); mbar_init(mb1, 1);
        mbar_arrive_expect(mb0, 0);
        mbar_arrive_expect(mb0, XT);
        mbar_arrive_expect(mb1, XT);
    }
    __syncthreads();
    asm volatile("barrier.cluster.arrive.aligned;" ::: "memory");
    asm volatile("barrier.cluster.wait.aligned;" ::: "memory");

    uint32_t r_s0 = 0, r_s1 = 0, r_m0 = 0, r_m1 = 0;
    if (w == 0 && lane < FC) {
        r_s0 = mapa_u32(smem_u32(&c_slot[0][rank]), lane);
        r_s1 = mapa_u32(smem_u32(&c_slot[1][rank]), lane);
        r_m0 = mapa_u32(mb0, lane);
        r_m1 = mapa_u32(mb1, lane);
    }

    float curx = shx[0], cury = shy[0], curz = shz[0];
    float* out = new_xyz + (size_t)b * SPT * 3;

    for (int s = 0; s < SPT; s++) {
        if (s > 0) {
            uint32_t mb = (s & 1) ? mb1 : mb0;
            mbar_wait(mb, (unsigned)((s >> 1) & 1));
            int bf = s & 1;
            uint64_t k0 = c_slot[bf][0], k1 = c_slot[bf][1];
            uint64_t k2 = c_slot[bf][2], k3 = c_slot[bf][3];
            uint64_t k4 = c_slot[bf][4], k5 = c_slot[bf][5];
            uint64_t k6 = c_slot[bf][6], k7 = c_slot[bf][7];
            uint64_t wk = u64max(u64max(u64max(k0, k1), u64max(k2, k3)),
                                 u64max(u64max(k4, k5), u64max(k6, k7)));
            int wi = (int)(~(uint32_t)wk);
            curx = shx[wi]; cury = shy[wi]; curz = shz[wi];
        }
        if (rank == 0 && t == 0) {
            out[s * 3 + 0] = curx;
            out[s * 3 + 1] = cury;
            out[s * 3 + 2] = curz;
        }
        float best = -1.0f; int bj = 0;
#pragma unroll
        for (int j = 0; j < FP; j++) {
            float dx = px[j] - curx, dy = py[j] - cury, dz = pz[j] - curz;
            float d = __fadd_rn(__fadd_rn(__fmul_rn(dx, dx), __fmul_rn(dy, dy)),
                                __fmul_rn(dz, dz));
            float nd = fminf(dist[j], d);
            dist[j] = nd;
            bool bt = nd > best;
            best = bt ? nd : best;
            bj = bt ? j : bj;
        }
        unsigned bi = (unsigned)(base + bj * FT + t);
        unsigned vb = __float_as_uint(best);
        unsigned mv = __reduce_max_sync(0xffffffffu, vb);
        unsigned cnd = (vb == mv) ? ~bi : 0u;
        unsigned ml = __reduce_max_sync(0xffffffffu, cnd);
        if (lane == 0) s_key[w] = ((uint64_t)mv << 32) | ml;
        __syncthreads();
        if (w == 0) {
            if (s + 1 < SPT) {
                unsigned hi = (lane < 8) ? (unsigned)(s_key[lane] >> 32) : 0u;
                unsigned lo = (lane < 8) ? (unsigned)s_key[lane] : 0u;
                unsigned mv2 = __reduce_max_sync(0xffffffffu, hi);
                unsigned c2 = (hi == mv2) ? lo : 0u;
                unsigned ml2 = __reduce_max_sync(0xffffffffu, c2);
                if (lane < FC) {
                    int st = (s + 1) & 1;
                    uint32_t rs = st ? r_s1 : r_s0;
                    uint32_t rm = st ? r_m1 : r_m0;
                    st_async_u64(rs, rm, ((uint64_t)mv2 << 32) | ml2);
                }
            }
            if (lane == 8 && s > 0 && s + 2 < SPT)
                mbar_arrive_expect((s & 1) ? mb1 : mb0, XT);
        }
    }
    asm volatile("barrier.cluster.arrive.aligned;" ::: "memory");
    asm volatile("barrier.cluster.wait.aligned;" ::: "memory");
}

// ============================================================================
// 2) FUSED kNN + conv1 (serial launch — overlap abandoned: NoC contention
//    from this kernel's streaming slowed FPS's DSMEM exchange by ~60%).
//    Block m: 8 warps compute warp-collective top-16 into smem, then the
//    block runs the 128x128 gemm1 (gather rows from smem knn) with fused
//    BN1-stats partials. DOUBLE-BUFFERED smem: one sync per k-tile.
// ============================================================================
__global__ __launch_bounds__(256, 2)
void fused_knn_gemm1(const float* __restrict__ newxyz, const float* __restrict__ feat,
                     const float* __restrict__ W, const float* __restrict__ bias,
                     float* __restrict__ Y, float* __restrict__ part) {
    const int K = 128;
    __shared__ float As[2][16][128];
    __shared__ float Ws[2][16][128];
    __shared__ int s_idx[128];
    int tid = threadIdx.x;
    int w = tid >> 5, lane = tid & 31;
    int m0 = blockIdx.x * 128;

    // ---- Phase A: kNN for this block's 8 queries (one per warp) ----
    {
        int g = blockIdx.x * 8 + w;
        int b = g >> 11;
        const float* sx = g_sx + (size_t)b * NPT;
        const float* sy = g_sy + (size_t)b * NPT;
        const float* sz = g_sz + (size_t)b * NPT;
        float qx = newxyz[(size_t)g * 3 + 0];
        float qy = newxyz[(size_t)g * 3 + 1];
        float qz = newxyz[(size_t)g * 3 + 2];

        float tv = (lane < 16) ? FLT_MAX : 0.0f;
        int   tix = 0;
        float ww = FLT_MAX;
        for (int i = 0; i < NPT / 32; i++) {
            int base = i << 5;
            float dx = sx[base + lane] - qx;
            float dy = sy[base + lane] - qy;
            float dz = sz[base + lane] - qz;
            float d = dx * dx + dy * dy + dz * dz;
            unsigned m = __ballot_sync(0xffffffffu, d < ww);
            while (m) {
                int src = __ffs(m) - 1; m &= m - 1;
                float dc = __shfl_sync(0xffffffffu, d, src);
                if (dc < ww) {
                    unsigned mv = __reduce_max_sync(0xffffffffu, __float_as_uint(tv));
                    unsigned own = __ballot_sync(0xffffffffu, __float_as_uint(tv) == mv) & 0xffffu;
                    if (lane == __ffs(own) - 1) { tv = dc; tix = base + src; }
                    ww = __uint_as_float(__reduce_max_sync(0xffffffffu, __float_as_uint(tv)));
                }
            }
        }
        if (lane < 16) s_idx[w * 16 + lane] = tix;
    }
    __syncthreads();

    // ---- Phase B: gemm1 for rows [m0, m0+128), gather from s_idx ----
    int tx = tid & 15, ty = tid >> 4;
    int lrow = tid & 127, khalf = tid >> 7;
    int kb = khalf * 8;

    const float* gfp;
    float gx0 = 0.0f, gx1 = 0.0f, gx2 = 0.0f;
    {
        int n = m0 + lrow;
        int g = n >> 4;
        int bb = g >> 11;
        int idx = s_idx[lrow];
        size_t p = (size_t)bb * NPT + idx;
        gfp = feat + p * DFEAT;
        if (khalf == 0) {
            gx0 = g_sx[p] - newxyz[(size_t)g * 3 + 0];
            gx1 = g_sy[p] - newxyz[(size_t)g * 3 + 1];
            gx2 = g_sz[p] - newxyz[(size_t)g * 3 + 2];
        }
    }

    float acc[8][8];
#pragma unroll
    for (int i = 0; i < 8; i++)
#pragma unroll
        for (int j = 0; j < 8; j++) acc[i][j] = 0.0f;

    // prologue: tile 0 -> buffer 0
    {
        float ar[8];
#pragma unroll
        for (int u = 0; u < 8; u++) {
            int cc = kb + u - 3;
            ar[u] = gfp[cc < 0 ? 0 : cc];
        }
        if (khalf == 0) { ar[0] = gx0; ar[1] = gx1; ar[2] = gx2; }
#pragma unroll
        for (int u = 0; u < 8; u++) As[0][kb + u][lrow] = ar[u];
        const float* wp = &W[(size_t)lrow * K + kb];
        float4 w0 = *(const float4*)wp;
        float4 w1 = *(const float4*)(wp + 4);
        Ws[0][kb + 0][lrow] = w0.x; Ws[0][kb + 1][lrow] = w0.y;
        Ws[0][kb + 2][lrow] = w0.z; Ws[0][kb + 3][lrow] = w0.w;
        Ws[0][kb + 4][lrow] = w1.x; Ws[0][kb + 5][lrow] = w1.y;
        Ws[0][kb + 6][lrow] = w1.z; Ws[0][kb + 7][lrow] = w1.w;
    }
    __syncthreads();

    for (int kt = 0; kt < 8; kt++) {
        int cur = kt & 1;
        float ar[8]; float4 w0, w1;
        if (kt < 7) {      // prefetch tile kt+1 into registers
            int kn = (kt + 1) * 16;
#pragma unroll
            for (int u = 0; u < 8; u++) ar[u] = gfp[kn + kb + u - 3];
            const float* wp = &W[(size_t)lrow * K + kn + kb];
            w0 = *(const float4*)wp;
            w1 = *(const float4*)(wp + 4);
        }
#pragma unroll
        for (int kk = 0; kk < 16; kk++) {
            float4 xa0 = *(const float4*)&As[cur][kk][ty * 8];
            float4 xa1 = *(const float4*)&As[cur][kk][ty * 8 + 4];
            float4 xb0 = *(const float4*)&Ws[cur][kk][tx * 8];
            float4 xb1 = *(const float4*)&Ws[cur][kk][tx * 8 + 4];
            float av[8] = {xa0.x, xa0.y, xa0.z, xa0.w, xa1.x, xa1.y, xa1.z, xa1.w};
            float bv[8] = {xb0.x, xb0.y, xb0.z, xb0.w, xb1.x, xb1.y, xb1.z, xb1.w};
#pragma unroll
            for (int i = 0; i < 8; i++)
#pragma unroll
                for (int j = 0; j < 8; j++) acc[i][j] += av[i] * bv[j];
        }
        if (kt < 7) {      // store tile kt+1 into the other buffer
            int nxt = cur ^ 1;
#pragma unroll
            for (int u = 0; u < 8; u++) As[nxt][kb + u][lrow] = ar[u];
            Ws[nxt][kb + 0][lrow] = w0.x; Ws[nxt][kb + 1][lrow] = w0.y;
            Ws[nxt][kb + 2][lrow] = w0.z; Ws[nxt][kb + 3][lrow] = w0.w;
            Ws[nxt][kb + 4][lrow] = w1.x; Ws[nxt][kb + 5][lrow] = w1.y;
            Ws[nxt][kb + 6][lrow] = w1.z; Ws[nxt][kb + 7][lrow] = w1.w;
        }
        __syncthreads();
    }
#pragma unroll
    for (int i = 0; i < 8; i++)
#pragma unroll
        for (int j = 0; j < 8; j++) acc[i][j] += bias[tx * 8 + j];

#pragma unroll
    for (int i = 0; i < 8; i++) {
        size_t row = (size_t)(m0 + ty * 8 + i) * C1 + tx * 8;
        float4 v0 = {acc[i][0], acc[i][1], acc[i][2], acc[i][3]};
        float4 v1 = {acc[i][4], acc[i][5], acc[i][6], acc[i][7]};
        *(float4*)&Y[row] = v0;
        *(float4*)&Y[row + 4] = v1;
    }
    // BN1 stats partials (reuse buffer 0/1)
    {
        float (*r0)[128] = As[0];
        float (*r1)[128] = Ws[0];
#pragma unroll
        for (int j = 0; j < 8; j++) {
            float s = 0.0f, q = 0.0f;
#pragma unroll
            for (int i = 0; i < 8; i++) { s += acc[i][j]; q += acc[i][j] * acc[i][j]; }
            r0[ty][tx * 8 + j] = s;
            r1[ty][tx * 8 + j] = q;
        }
        __syncthreads();
        if (tid < 128) {
            float S = 0.0f, Q = 0.0f;
#pragma unroll
            for (int i = 0; i < 16; i++) { S += r0[i][tid]; Q += r1[i][tid]; }
            size_t o = (size_t)blockIdx.x * C1 + tid;
            part[o] = S;
            part[PSQ_OFF + o] = Q;
        }
    }
}

// ============================================================================
// 3) GEMM2: fuseA (BN1+ReLU on input), group-max + BN2-stats epilogue, no Y.
//    128x128 tile, 8x8 register tile, DOUBLE-BUFFERED smem (1 sync / k-tile).
// ============================================================================
__global__ __launch_bounds__(256, 2)
void gemm2_kernel(const float* __restrict__ A, const float* __restrict__ W,
                  const float* __restrict__ bias,
                  const float* __restrict__ aScale, const float* __restrict__ aBias,
                  float* __restrict__ gmax, float* __restrict__ part) {
    const int K = 128;
    const int Nout = C2;
    __shared__ float As[2][16][128];
    __shared__ float Ws[2][16][128];
    int m0 = blockIdx.x * 128;
    int c0 = blockIdx.y * 128;
    int tid = threadIdx.x;
    int tx = tid & 15, ty = tid >> 4;
    int lrow = tid & 127, khalf = tid >> 7;
    int kb = khalf * 8;

    float acc[8][8];
#pragma unroll
    for (int i = 0; i < 8; i++)
#pragma unroll
        for (int j = 0; j < 8; j++) acc[i][j] = 0.0f;

    // prologue: tile 0 -> buffer 0 (with fused BN1+ReLU on A)
    {
        const float* ap = &A[(size_t)(m0 + lrow) * K + kb];
        float4 a0 = *(const float4*)ap;
        float4 a1 = *(const float4*)(ap + 4);
        float ar[8] = {a0.x, a0.y, a0.z, a0.w, a1.x, a1.y, a1.z, a1.w};
#pragma unroll
        for (int u = 0; u < 8; u++)
            As[0][kb + u][lrow] = fmaxf(fmaf(ar[u], aScale[kb + u], aBias[kb + u]), 0.0f);
        const float* wp = &W[(size_t)(c0 + lrow) * K + kb];
        float4 w0 = *(const float4*)wp;
        float4 w1 = *(const float4*)(wp + 4);
        Ws[0][kb + 0][lrow] = w0.x; Ws[0][kb + 1][lrow] = w0.y;
        Ws[0][kb + 2][lrow] = w0.z; Ws[0][kb + 3][lrow] = w0.w;
        Ws[0][kb + 4][lrow] = w1.x; Ws[0][kb + 5][lrow] = w1.y;
        Ws[0][kb + 6][lrow] = w1.z; Ws[0][kb + 7][lrow] = w1.w;
    }
    __syncthreads();

    for (int kt = 0; kt < 8; kt++) {
        int cur = kt & 1;
        float4 a0, a1, w0, w1;
        if (kt < 7) {
            int kn = (kt + 1) * 16;
            const float* ap = &A[(size_t)(m0 + lrow) * K + kn + kb];
            a0 = *(const float4*)ap;
            a1 = *(const float4*)(ap + 4);
            const float* wp = &W[(size_t)(c0 + lrow) * K + kn + kb];
            w0 = *(const float4*)wp;
            w1 = *(const float4*)(wp + 4);
        }
#pragma unroll
        for (int kk = 0; kk < 16; kk++) {
            float4 xa0 = *(const float4*)&As[cur][kk][ty * 8];
            float4 xa1 = *(const float4*)&As[cur][kk][ty * 8 + 4];
            float4 xb0 = *(const float4*)&Ws[cur][kk][tx * 8];
            float4 xb1 = *(const float4*)&Ws[cur][kk][tx * 8 + 4];
            float av[8] = {xa0.x, xa0.y, xa0.z, xa0.w, xa1.x, xa1.y, xa1.z, xa1.w};
            float bv[8] = {xb0.x, xb0.y, xb0.z, xb0.w, xb1.x, xb1.y, xb1.z, xb1.w};
#pragma unroll
            for (int i = 0; i < 8; i++)
#pragma unroll
                for (int j = 0; j < 8; j++) acc[i][j] += av[i] * bv[j];
        }
        if (kt < 7) {
            int nxt = cur ^ 1;
            int kn = (kt + 1) * 16;
            float ar[8] = {a0.x, a0.y, a0.z, a0.w, a1.x, a1.y, a1.z, a1.w};
#pragma unroll
            for (int u = 0; u < 8; u++)
                As[nxt][kb + u][lrow] =
                    fmaxf(fmaf(ar[u], aScale[kn + kb + u], aBias[kn + kb + u]), 0.0f);
            Ws[nxt][kb + 0][lrow] = w0.x; Ws[nxt][kb + 1][lrow] = w0.y;
            Ws[nxt][kb + 2][lrow] = w0.z; Ws[nxt][kb + 3][lrow] = w0.w;
            Ws[nxt][kb + 4][lrow] = w1.x; Ws[nxt][kb + 5][lrow] = w1.y;
            Ws[nxt][kb + 6][lrow] = w1.z; Ws[nxt][kb + 7][lrow] = w1.w;
        }
        __syncthreads();
    }
#pragma unroll
    for (int i = 0; i < 8; i++)
#pragma unroll
        for (int j = 0; j < 8; j++) acc[i][j] += bias[c0 + tx * 8 + j];

    // group-of-16 max epilogue
    {
        float (*redm)[128] = As[0];
#pragma unroll
        for (int j = 0; j < 8; j++) {
            float m = acc[0][j];
#pragma unroll
            for (int i = 1; i < 8; i++) m = fmaxf(m, acc[i][j]);
            redm[ty][tx * 8 + j] = m;
        }
        __syncthreads();
        if (ty < 8) {
#pragma unroll
            for (int j = 0; j < 8; j++) {
                int c = tx * 8 + j;
                float m = fmaxf(redm[2 * ty][c], redm[2 * ty + 1][c]);
                gmax[(size_t)(m0 / 16 + ty) * Nout + c0 + c] = m;
            }
        }
        __syncthreads();
    }
    // BN2 stats partials
    {
        float (*r0)[128] = As[0];
        float (*r1)[128] = Ws[0];
#pragma unroll
        for (int j = 0; j < 8; j++) {
            float s = 0.0f, q = 0.0f;
#pragma unroll
            for (int i = 0; i < 8; i++) { s += acc[i][j]; q += acc[i][j] * acc[i][j]; }
            r0[ty][tx * 8 + j] = s;
            r1[ty][tx * 8 + j] = q;
        }
        __syncthreads();
        if (tid < 128) {
            float S = 0.0f, Q = 0.0f;
#pragma unroll
            for (int i = 0; i < 16; i++) { S += r0[i][tid]; Q += r1[i][tid]; }
            size_t o = (size_t)blockIdx.x * Nout + c0 + tid;
            part[o] = S;
            part[PSQ_OFF + o] = Q;
        }
    }
}

// ============================================================================
// 4) BN stats reduction + finalize
// ============================================================================
__global__ void reduce_kernel(const float* __restrict__ part, float* __restrict__ red, int C) {
    int c = threadIdx.x;
    int r = blockIdx.x;
    float S = 0.0f, Q = 0.0f;
    for (int m = r * 32; m < r * 32 + 32; m++) {
        size_t o = (size_t)m * C + c;
        S += part[o];
        Q += part[PSQ_OFF + o];
    }
    red[r * C + c] = S;
    red[RSQ_OFF + r * C + c] = Q;
}

__global__ void finalize_kernel(const float* __restrict__ red,
                                const float* __restrict__ gamma,
                                const float* __restrict__ beta,
                                float* __restrict__ scale, float* __restrict__ bias, int C) {
    int c = threadIdx.x;
    float s = 0.0f, q = 0.0f;
    for (int r = 0; r < 32; r++) {
        s += red[r * C + c];
        q += red[RSQ_OFF + r * C + c];
    }
    const float inv = 1.0f / (float)MROWS;
    float m = s * inv;
    float v = q * inv - m * m;
    float sc = gamma[c] * rsqrtf(v + 1e-5f);
    scale[c] = sc;
    bias[c] = beta[c] - m * sc;
}

// ============================================================================
// 5) BN2 + ReLU on the pre-reduced group max (monotone: scale > 0).
// ============================================================================
__global__ __launch_bounds__(256, 4)
void maxpool_kernel(const float* __restrict__ gmax, const float* __restrict__ scale,
                    const float* __restrict__ bias, float* __restrict__ out) {
    int g = blockIdx.x;
    int c = threadIdx.x;
    float v = fmaf(gmax[(size_t)g * C2 + c], scale[c], bias[c]);
    out[(size_t)g * C2 + c] = fmaxf(v, 0.0f);
}

// ============================================================================
extern "C" void kernel_launch(void* const* d_in, const int* in_sizes, int n_in,
                              void* d_out, int out_size) {
    const float* xyz    = (const float*)d_in[0];
    const float* feat   = (const float*)d_in[1];
    const float* W1     = (const float*)d_in[2];
    const float* b1     = (const float*)d_in[3];
    const float* gamma1 = (const float*)d_in[4];
    const float* beta1  = (const float*)d_in[5];
    const float* W2     = (const float*)d_in[6];
    const float* b2     = (const float*)d_in[7];
    const float* gamma2 = (const float*)d_in[8];
    const float* beta2  = (const float*)d_in[9];

    float* out = (float*)d_out;
    float* out_newxyz = out;                            // [B,S,3]
    float* out_x      = out + (size_t)BATCH * SPT * 3;  // [B,S,C2]

    float *y1, *gmax, *part, *red, *scale, *bias;
    cudaGetSymbolAddress((void**)&y1,    g_y1);
    cudaGetSymbolAddress((void**)&gmax,  g_max);
    cudaGetSymbolAddress((void**)&part,  g_part);
    cudaGetSymbolAddress((void**)&red,   g_red);
    cudaGetSymbolAddress((void**)&scale, g_scale);
    cudaGetSymbolAddress((void**)&bias,  g_bias);

    // 0. SoA transpose of xyz
    soa_kernel<<<(BATCH * NPT) / 256, 256>>>(xyz);
    // 1. FPS (cluster kernel; writes new_xyz directly to output)
    cudaFuncSetAttribute(fps_cluster_kernel,
                         cudaFuncAttributeMaxDynamicSharedMemorySize, FPS_SMEM);
    fps_cluster_kernel<<<BATCH * FC, FT, FPS_SMEM>>>(out_newxyz);
    // 2. fused kNN + conv1 (serial; fused BN1-stats partials)
    fused_knn_gemm1<<<MBLK, 256>>>(out_newxyz, feat, W1, b1, y1, part);
    reduce_kernel<<<32, C1>>>(part, red, C1);
    finalize_kernel<<<1, C1>>>(red, gamma1, beta1, scale, bias, C1);
    // 3. conv2: fused BN1+ReLU input, group-max + BN2-stats epilogue
    {
        dim3 grid(MBLK, C2 / 128);
        gemm2_kernel<<<grid, 256>>>(y1, W2, b2, scale, bias, gmax, part);
    }
    reduce_kernel<<<32, C2>>>(part, red, C2);
    finalize_kernel<<<1, C2>>>(red, gamma2, beta2, scale, bias, C2);
    // 4. BN2+ReLU on pre-reduced max -> output
    maxpool_kernel<<<BATCH * SPT, C2>>>(gmax, scale, bias, out_x);
}

// round 16
// speedup vs baseline: 1.6538x; 1.2086x over previous
#include <cuda_runtime.h>
#include <cuda_bf16.h>
#include <cstdint>
#include <float.h>

// Problem constants (shapes fixed by the dataset)
#define BATCH 4
#define NPT   16384
#define SPT   2048
#define KNN   16
#define DFEAT 125
#define C0    128
#define C1    128
#define C2    256
#define MROWS (BATCH * SPT * KNN)   // 131072 samples through the MLP
#define MBLK  (MROWS / 128)         // 1024 gemm m-blocks (128-row tiles)
#define PSQ_OFF (MBLK * 256)        // sumsq offset inside g_part
#define RSQ_OFF (32 * 256)          // sumsq offset inside g_red

// FPS cluster config: 8 CTAs x 256 threads per batch
#define FC 8
#define FT 256
#define FP (NPT / FC / FT)          // 8 points per thread
#define XT (FC * 8)                 // tx bytes per exchange (8 sources x 8B)
#define FPS_SMEM (3 * NPT * 4)      // full batch xyz in SMEM (192 KB)

// ---------------- scratch (static device globals; no allocation allowed) ----
__device__ float g_y1[(size_t)MROWS * C1];     // conv1 out (raw, pre-BN)
__device__ float g_max[(size_t)BATCH * SPT * C2]; // raw per-group max (8.4MB)
__device__ float g_part[2 * MBLK * 256];       // per-mblock [sum | sumsq]
__device__ float g_red[2 * 32 * 256];          // stage-1 reduced partials
__device__ float g_scale[256];
__device__ float g_bias[256];
__device__ int   g_knn[BATCH * SPT * KNN];
__device__ float g_sx[BATCH * NPT];            // SoA xyz
__device__ float g_sy[BATCH * NPT];
__device__ float g_sz[BATCH * NPT];

// ---------------------------------------------------------------------------
// helpers: DSMEM / mbarrier
// ---------------------------------------------------------------------------
__device__ __forceinline__ uint32_t smem_u32(const void* p) {
    return (uint32_t)__cvta_generic_to_shared(p);
}
__device__ __forceinline__ uint32_t mapa_u32(uint32_t addr, uint32_t rank) {
    uint32_t r;
    asm("mapa.shared::cluster.u32 %0, %1, %2;" : "=r"(r) : "r"(addr), "r"(rank));
    return r;
}
__device__ __forceinline__ void st_async_u64(uint32_t raddr, uint32_t rmbar, uint64_t v) {
    asm volatile("st.async.shared::cluster.mbarrier::complete_tx::bytes.b64 [%0], %1, [%2];"
                 :: "r"(raddr), "l"(v), "r"(rmbar) : "memory");
}
__device__ __forceinline__ void mbar_inval(uint32_t a) {
    asm volatile("mbarrier.inval.shared.b64 [%0];" :: "r"(a) : "memory");
}
__device__ __forceinline__ void mbar_init(uint32_t a, uint32_t cnt) {
    asm volatile("mbarrier.init.shared.b64 [%0], %1;" :: "r"(a), "r"(cnt) : "memory");
}
__device__ __forceinline__ void mbar_arrive_expect(uint32_t a, uint32_t tx) {
    asm volatile("mbarrier.arrive.expect_tx.shared.b64 _, [%0], %1;"
                 :: "r"(a), "r"(tx) : "memory");
}
__device__ __forceinline__ void mbar_wait(uint32_t mbar, uint32_t parity) {
    asm volatile(
        "{\n\t.reg .pred P;\n\t"
        "WAIT_%=:\n\t"
        "mbarrier.try_wait.parity.acquire.cluster.shared::cta.b64 P, [%0], %1, 0x989680;\n\t"
        "@P bra.uni DONE_%=;\n\t"
        "bra.uni WAIT_%=;\n\t"
        "DONE_%=:\n\t}"
        :: "r"(mbar), "r"(parity) : "memory");
}
__device__ __forceinline__ uint64_t u64max(uint64_t a, uint64_t b) {
    return (a > b) ? a : b;
}
// packed f32x2 helpers (FFMA2 — ptxas never auto-emits; PTX-only)
__device__ __forceinline__ uint64_t pack2(float lo, float hi) {
    uint64_t v;
    asm("mov.b64 %0, {%1, %2};" : "=l"(v) : "f"(lo), "f"(hi));
    return v;
}
__device__ __forceinline__ void unpack2(uint64_t v, float& lo, float& hi) {
    asm("mov.b64 {%0, %1}, %2;" : "=f"(lo), "=f"(hi) : "l"(v));
}
__device__ __forceinline__ void fma2(uint64_t& d, uint64_t a, uint64_t b) {
    asm("fma.rn.f32x2 %0, %1, %2, %0;" : "+l"(d) : "l"(a), "l"(b));
}

// ============================================================================
// 0) AoS -> SoA transpose of xyz (coalesced via smem staging)
// ============================================================================
__global__ __launch_bounds__(256)
void soa_kernel(const float* __restrict__ xyz) {
    __shared__ float buf[768];
    int t = threadIdx.x;
    size_t base = (size_t)blockIdx.x * 768;
#pragma unroll
    for (int r = 0; r < 3; r++) buf[t + 256 * r] = xyz[base + t + 256 * r];
    __syncthreads();
    size_t o = (size_t)blockIdx.x * 256 + t;
    g_sx[o] = buf[t * 3 + 0];
    g_sy[o] = buf[t * 3 + 1];
    g_sz[o] = buf[t * 3 + 2];
}

// ============================================================================
// 1) FPS (R10/R11 protocol — best measured variant, unchanged).
// ============================================================================
__global__ __launch_bounds__(FT, 1) __cluster_dims__(FC, 1, 1)
void fps_cluster_kernel(float* __restrict__ new_xyz) {
    extern __shared__ float smem[];
    float* shx = smem;
    float* shy = smem + NPT;
    float* shz = smem + 2 * NPT;

    int b = blockIdx.x / FC;
    int rank = blockIdx.x % FC;
    int t = threadIdx.x;
    int w = t >> 5, lane = t & 31;
    int base = rank * (NPT / FC);
    const float* sx = g_sx + (size_t)b * NPT;
    const float* sy = g_sy + (size_t)b * NPT;
    const float* sz = g_sz + (size_t)b * NPT;

    for (int i = t; i < NPT; i += FT) {
        shx[i] = sx[i]; shy[i] = sy[i]; shz[i] = sz[i];
    }

    float px[FP], py[FP], pz[FP], dist[FP];
#pragma unroll
    for (int j = 0; j < FP; j++) {
        int i = base + j * FT + t;
        px[j] = sx[i]; py[j] = sy[i]; pz[j] = sz[i];
        dist[j] = 1e10f;
    }

    __shared__ __align__(8) uint64_t c_slot[2][FC];
    __shared__ __align__(8) uint64_t mbar[2];
    __shared__ __align__(8) uint64_t s_key[8];

    uint32_t mb0 = smem_u32(&mbar[0]);
    uint32_t mb1 = smem_u32(&mbar[1]);

    if (t == 0) {
        mbar_inval(mb0); mbar_inval(mb1);
        mbar_init(mb0, 1); mbar_init(mb1, 1);
        mbar_arrive_expect(mb0, 0);
        mbar_arrive_expect(mb0, XT);
        mbar_arrive_expect(mb1, XT);
    }
    __syncthreads();
    asm volatile("barrier.cluster.arrive.aligned;" ::: "memory");
    asm volatile("barrier.cluster.wait.aligned;" ::: "memory");

    uint32_t r_s0 = 0, r_s1 = 0, r_m0 = 0, r_m1 = 0;
    if (w == 0 && lane < FC) {
        r_s0 = mapa_u32(smem_u32(&c_slot[0][rank]), lane);
        r_s1 = mapa_u32(smem_u32(&c_slot[1][rank]), lane);
        r_m0 = mapa_u32(mb0, lane);
        r_m1 = mapa_u32(mb1, lane);
    }

    float curx = shx[0], cury = shy[0], curz = shz[0];
    float* out = new_xyz + (size_t)b * SPT * 3;

    for (int s = 0; s < SPT; s++) {
        if (s > 0) {
            uint32_t mb = (s & 1) ? mb1 : mb0;
            mbar_wait(mb, (unsigned)((s >> 1) & 1));
            int bf = s & 1;
            uint64_t k0 = c_slot[bf][0], k1 = c_slot[bf][1];
            uint64_t k2 = c_slot[bf][2], k3 = c_slot[bf][3];
            uint64_t k4 = c_slot[bf][4], k5 = c_slot[bf][5];
            uint64_t k6 = c_slot[bf][6], k7 = c_slot[bf][7];
            uint64_t wk = u64max(u64max(u64max(k0, k1), u64max(k2, k3)),
                                 u64max(u64max(k4, k5), u64max(k6, k7)));
            int wi = (int)(~(uint32_t)wk);
            curx = shx[wi]; cury = shy[wi]; curz = shz[wi];
        }
        if (rank == 0 && t == 0) {
            out[s * 3 + 0] = curx;
            out[s * 3 + 1] = cury;
            out[s * 3 + 2] = curz;
        }
        float best = -1.0f; int bj = 0;
#pragma unroll
        for (int j = 0; j < FP; j++) {
            float dx = px[j] - curx, dy = py[j] - cury, dz = pz[j] - curz;
            float d = __fadd_rn(__fadd_rn(__fmul_rn(dx, dx), __fmul_rn(dy, dy)),
                                __fmul_rn(dz, dz));
            float nd = fminf(dist[j], d);
            dist[j] = nd;
            bool bt = nd > best;
            best = bt ? nd : best;
            bj = bt ? j : bj;
        }
        unsigned bi = (unsigned)(base + bj * FT + t);
        unsigned vb = __float_as_uint(best);
        unsigned mv = __reduce_max_sync(0xffffffffu, vb);
        unsigned cnd = (vb == mv) ? ~bi : 0u;
        unsigned ml = __reduce_max_sync(0xffffffffu, cnd);
        if (lane == 0) s_key[w] = ((uint64_t)mv << 32) | ml;
        __syncthreads();
        if (w == 0) {
            if (s + 1 < SPT) {
                unsigned hi = (lane < 8) ? (unsigned)(s_key[lane] >> 32) : 0u;
                unsigned lo = (lane < 8) ? (unsigned)s_key[lane] : 0u;
                unsigned mv2 = __reduce_max_sync(0xffffffffu, hi);
                unsigned c2 = (hi == mv2) ? lo : 0u;
                unsigned ml2 = __reduce_max_sync(0xffffffffu, c2);
                if (lane < FC) {
                    int st = (s + 1) & 1;
                    uint32_t rs = st ? r_s1 : r_s0;
                    uint32_t rm = st ? r_m1 : r_m0;
                    st_async_u64(rs, rm, ((uint64_t)mv2 << 32) | ml2);
                }
            }
            if (lane == 8 && s > 0 && s + 2 < SPT)
                mbar_arrive_expect((s & 1) ? mb1 : mb0, XT);
        }
    }
    asm volatile("barrier.cluster.arrive.aligned;" ::: "memory");
    asm volatile("barrier.cluster.wait.aligned;" ::: "memory");
}

// ============================================================================
// 2) kNN (k=16): warp-collective top-16 (R11, unchanged).
// ============================================================================
__global__ __launch_bounds__(256)
void knn_kernel(const float* __restrict__ new_xyz, int* __restrict__ knn) {
    int w = threadIdx.x >> 5, lane = threadIdx.x & 31;
    int g = blockIdx.x * 8 + w;     // query id 0..8191
    int b = g >> 11;
    const float* sx = g_sx + (size_t)b * NPT;
    const float* sy = g_sy + (size_t)b * NPT;
    const float* sz = g_sz + (size_t)b * NPT;
    float qx = new_xyz[(size_t)g * 3 + 0];
    float qy = new_xyz[(size_t)g * 3 + 1];
    float qz = new_xyz[(size_t)g * 3 + 2];

    float tv = (lane < 16) ? FLT_MAX : 0.0f;
    int   tix = 0;
    float ww = FLT_MAX;

    for (int i = 0; i < NPT / 32; i++) {
        int base = i << 5;
        float dx = sx[base + lane] - qx;
        float dy = sy[base + lane] - qy;
        float dz = sz[base + lane] - qz;
        float d = dx * dx + dy * dy + dz * dz;
        unsigned m = __ballot_sync(0xffffffffu, d < ww);
        while (m) {
            int src = __ffs(m) - 1; m &= m - 1;
            float dc = __shfl_sync(0xffffffffu, d, src);
            if (dc < ww) {
                unsigned mv = __reduce_max_sync(0xffffffffu, __float_as_uint(tv));
                unsigned own = __ballot_sync(0xffffffffu, __float_as_uint(tv) == mv) & 0xffffu;
                if (lane == __ffs(own) - 1) { tv = dc; tix = base + src; }
                ww = __uint_as_float(__reduce_max_sync(0xffffffffu, __float_as_uint(tv)));
            }
        }
    }
    if (lane < 16) knn[(size_t)g * 16 + lane] = tix;
}

// ============================================================================
// 3) GEMM (R11 structure, inner loop upgraded to packed fma.rn.f32x2):
//    accumulator packed along the row (i) dimension -> a2 pairs load straight
//    from As as u64 (contiguous rows), b duplicated into both halves via mov.
//    32 FFMA2 per kk replace 64 FFMA: fma-pipe time halves. Numerics = fma.
//    Fusions: fuseGather (layer-1 gather), fuseA (BN1+ReLU on A),
//    fuseMax (group-of-16 max -> gmax), fuseStats (BN partials -> part).
// ============================================================================
__global__ __launch_bounds__(256, 2)
void gemm_kernel(const float* __restrict__ A, const float* __restrict__ W,
                 const float* __restrict__ bias, float* __restrict__ Y, int Nout,
                 const float* __restrict__ aScale, const float* __restrict__ aBias,
                 int fuseA, float* __restrict__ gmax, int fuseMax,
                 float* __restrict__ part, int fuseStats,
                 const float* __restrict__ feat, const int* __restrict__ knni,
                 const float* __restrict__ newxyz, int fuseGather) {
    const int K = 128;
    __shared__ float As[16][128];
    __shared__ float Ws[16][128];
    int m0 = blockIdx.x * 128;
    int c0 = blockIdx.y * 128;
    int tid = threadIdx.x;
    int tx = tid & 15, ty = tid >> 4;
    int lrow = tid & 127, khalf = tid >> 7;
    int kb = khalf * 8;

    // gather-mode row sources (layer 1)
    const float* gfp = nullptr;
    float gx0 = 0.0f, gx1 = 0.0f, gx2 = 0.0f;
    if (fuseGather) {
        int n = m0 + lrow;
        int g = n >> 4;
        int bb = g >> 11;
        int idx = knni[n];
        size_t p = (size_t)bb * NPT + idx;
        gfp = feat + p * DFEAT;
        if (khalf == 0) {
            gx0 = g_sx[p] - newxyz[(size_t)g * 3 + 0];
            gx1 = g_sy[p] - newxyz[(size_t)g * 3 + 1];
            gx2 = g_sz[p] - newxyz[(size_t)g * 3 + 2];
        }
    }

    uint64_t acc2[4][8];
#pragma unroll
    for (int i = 0; i < 4; i++)
#pragma unroll
        for (int j = 0; j < 8; j++) acc2[i][j] = 0ull;

    // ---- prefetch A k-tile 0 into registers ----
    float ar[8];
    if (fuseGather) {
#pragma unroll
        for (int u = 0; u < 8; u++) {
            int cc = kb + u - 3;
            ar[u] = gfp[cc < 0 ? 0 : cc];
        }
        if (khalf == 0) { ar[0] = gx0; ar[1] = gx1; ar[2] = gx2; }
    } else {
        const float* ap = &A[(size_t)(m0 + lrow) * K + kb];
        float4 a0 = *(const float4*)ap;
        float4 a1 = *(const float4*)(ap + 4);
        ar[0] = a0.x; ar[1] = a0.y; ar[2] = a0.z; ar[3] = a0.w;
        ar[4] = a1.x; ar[5] = a1.y; ar[6] = a1.z; ar[7] = a1.w;
    }

    for (int kt = 0; kt < 8; kt++) {
        int k0 = kt * 16;
#pragma unroll
        for (int u = 0; u < 8; u++) {
            float x = ar[u];
            if (fuseA)
                x = fmaxf(fmaf(x, aScale[k0 + kb + u], aBias[k0 + kb + u]), 0.0f);
            As[kb + u][lrow] = x;
        }
        {
            const float* wp = &W[(size_t)(c0 + lrow) * K + k0 + kb];
            float4 w0 = *(const float4*)wp;
            float4 w1 = *(const float4*)(wp + 4);
            Ws[kb + 0][lrow] = w0.x; Ws[kb + 1][lrow] = w0.y;
            Ws[kb + 2][lrow] = w0.z; Ws[kb + 3][lrow] = w0.w;
            Ws[kb + 4][lrow] = w1.x; Ws[kb + 5][lrow] = w1.y;
            Ws[kb + 6][lrow] = w1.z; Ws[kb + 7][lrow] = w1.w;
        }
        __syncthreads();
        if (kt < 7) {
            int kn = k0 + 16;
            if (fuseGather) {
#pragma unroll
                for (int u = 0; u < 8; u++) ar[u] = gfp[kn + kb + u - 3];
            } else {
                const float* ap = &A[(size_t)(m0 + lrow) * K + kn + kb];
                float4 a0 = *(const float4*)ap;
                float4 a1 = *(const float4*)(ap + 4);
                ar[0] = a0.x; ar[1] = a0.y; ar[2] = a0.z; ar[3] = a0.w;
                ar[4] = a1.x; ar[5] = a1.y; ar[6] = a1.z; ar[7] = a1.w;
            }
        }
#pragma unroll
        for (int kk = 0; kk < 16; kk++) {
            // a pairs: rows (ty*8+2i, ty*8+2i+1) -- contiguous in As
            const uint64_t* ap64 = (const uint64_t*)&As[kk][ty * 8];
            uint64_t a20 = ap64[0], a21 = ap64[1], a22 = ap64[2], a23 = ap64[3];
            float4 xb0 = *(const float4*)&Ws[kk][tx * 8];
            float4 xb1 = *(const float4*)&Ws[kk][tx * 8 + 4];
            uint64_t b2[8];
            b2[0] = pack2(xb0.x, xb0.x); b2[1] = pack2(xb0.y, xb0.y);
            b2[2] = pack2(xb0.z, xb0.z); b2[3] = pack2(xb0.w, xb0.w);
            b2[4] = pack2(xb1.x, xb1.x); b2[5] = pack2(xb1.y, xb1.y);
            b2[6] = pack2(xb1.z, xb1.z); b2[7] = pack2(xb1.w, xb1.w);
#pragma unroll
            for (int j = 0; j < 8; j++) {
                fma2(acc2[0][j], a20, b2[j]);
                fma2(acc2[1][j], a21, b2[j]);
                fma2(acc2[2][j], a22, b2[j]);
                fma2(acc2[3][j], a23, b2[j]);
            }
        }
        __syncthreads();
    }

    // unpack packed accumulators: acc[2*i2 + lo/hi][j]
    float acc[8][8];
#pragma unroll
    for (int i2 = 0; i2 < 4; i2++)
#pragma unroll
        for (int j = 0; j < 8; j++)
            unpack2(acc2[i2][j], acc[2 * i2][j], acc[2 * i2 + 1][j]);

#pragma unroll
    for (int i = 0; i < 8; i++)
#pragma unroll
        for (int j = 0; j < 8; j++) acc[i][j] += bias[c0 + tx * 8 + j];

    if (Y) {
#pragma unroll
        for (int i = 0; i < 8; i++) {
            size_t row = (size_t)(m0 + ty * 8 + i) * Nout + c0 + tx * 8;
            float4 v0 = {acc[i][0], acc[i][1], acc[i][2], acc[i][3]};
            float4 v1 = {acc[i][4], acc[i][5], acc[i][6], acc[i][7]};
            *(float4*)&Y[row] = v0;
            *(float4*)&Y[row + 4] = v1;
        }
    }
    if (fuseMax) {
        float (*redm)[128] = As;
#pragma unroll
        for (int j = 0; j < 8; j++) {
            float m = acc[0][j];
#pragma unroll
            for (int i = 1; i < 8; i++) m = fmaxf(m, acc[i][j]);
            redm[ty][tx * 8 + j] = m;
        }
        __syncthreads();
        if (ty < 8) {
#pragma unroll
            for (int j = 0; j < 8; j++) {
                int c = tx * 8 + j;
                float m = fmaxf(redm[2 * ty][c], redm[2 * ty + 1][c]);
                gmax[(size_t)(m0 / 16 + ty) * Nout + c0 + c] = m;
            }
        }
        __syncthreads();
    }
    if (fuseStats) {
        float (*r0)[128] = As;
        float (*r1)[128] = Ws;
#pragma unroll
        for (int j = 0; j < 8; j++) {
            float s = 0.0f, q = 0.0f;
#pragma unroll
            for (int i = 0; i < 8; i++) { s += acc[i][j]; q += acc[i][j] * acc[i][j]; }
            r0[ty][tx * 8 + j] = s;
            r1[ty][tx * 8 + j] = q;
        }
        __syncthreads();
        if (tid < 128) {
            float S = 0.0f, Q = 0.0f;
#pragma unroll
            for (int i = 0; i < 16; i++) { S += r0[i][tid]; Q += r1[i][tid]; }
            size_t o = (size_t)(m0 / 128) * Nout + c0 + tid;
            part[o] = S;
            part[PSQ_OFF + o] = Q;
        }
    }
}

// ============================================================================
// 4) BN stats reduction + finalize
// ============================================================================
__global__ void reduce_kernel(const float* __restrict__ part, float* __restrict__ red, int C) {
    int c = threadIdx.x;
    int r = blockIdx.x;
    float S = 0.0f, Q = 0.0f;
    for (int m = r * 32; m < r * 32 + 32; m++) {
        size_t o = (size_t)m * C + c;
        S += part[o];
        Q += part[PSQ_OFF + o];
    }
    red[r * C + c] = S;
    red[RSQ_OFF + r * C + c] = Q;
}

__global__ void finalize_kernel(const float* __restrict__ red,
                                const float* __restrict__ gamma,
                                const float* __restrict__ beta,
                                float* __restrict__ scale, float* __restrict__ bias, int C) {
    int c = threadIdx.x;
    float s = 0.0f, q = 0.0f;
    for (int r = 0; r < 32; r++) {
        s += red[r * C + c];
        q += red[RSQ_OFF + r * C + c];
    }
    const float inv = 1.0f / (float)MROWS;
    float m = s * inv;
    float v = q * inv - m * m;
    float sc = gamma[c] * rsqrtf(v + 1e-5f);
    scale[c] = sc;
    bias[c] = beta[c] - m * sc;
}

// ============================================================================
// 5) BN2 + ReLU on the pre-reduced group max (monotone: scale > 0).
// ============================================================================
__global__ __launch_bounds__(256, 4)
void maxpool_kernel(const float* __restrict__ gmax, const float* __restrict__ scale,
                    const float* __restrict__ bias, float* __restrict__ out) {
    int g = blockIdx.x;
    int c = threadIdx.x;
    float v = fmaf(gmax[(size_t)g * C2 + c], scale[c], bias[c]);
    out[(size_t)g * C2 + c] = fmaxf(v, 0.0f);
}

// ============================================================================
extern "C" void kernel_launch(void* const* d_in, const int* in_sizes, int n_in,
                              void* d_out, int out_size) {
    const float* xyz    = (const float*)d_in[0];
    const float* feat   = (const float*)d_in[1];
    const float* W1     = (const float*)d_in[2];
    const float* b1     = (const float*)d_in[3];
    const float* gamma1 = (const float*)d_in[4];
    const float* beta1  = (const float*)d_in[5];
    const float* W2     = (const float*)d_in[6];
    const float* b2     = (const float*)d_in[7];
    const float* gamma2 = (const float*)d_in[8];
    const float* beta2  = (const float*)d_in[9];

    float* out = (float*)d_out;
    float* out_newxyz = out;                            // [B,S,3]
    float* out_x      = out + (size_t)BATCH * SPT * 3;  // [B,S,C2]

    float *y1, *gmax, *part, *red, *scale, *bias;
    int *knni;
    cudaGetSymbolAddress((void**)&y1,    g_y1);
    cudaGetSymbolAddress((void**)&gmax,  g_max);
    cudaGetSymbolAddress((void**)&part,  g_part);
    cudaGetSymbolAddress((void**)&red,   g_red);
    cudaGetSymbolAddress((void**)&scale, g_scale);
    cudaGetSymbolAddress((void**)&bias,  g_bias);
    cudaGetSymbolAddress((void**)&knni,  g_knn);

    // 0. SoA transpose of xyz
    soa_kernel<<<(BATCH * NPT) / 256, 256>>>(xyz);
    // 1. FPS (cluster kernel; writes new_xyz directly to output)
    cudaFuncSetAttribute(fps_cluster_kernel,
                         cudaFuncAttributeMaxDynamicSharedMemorySize, FPS_SMEM);
    fps_cluster_kernel<<<BATCH * FC, FT, FPS_SMEM>>>(out_newxyz);
    // 2. kNN (warp-collective top-16)
    knn_kernel<<<(BATCH * SPT) / 8, 256>>>(out_newxyz, knni);
    // 3. conv1: fused gather input, fused BN1-stats partials
    {
        dim3 grid(MBLK, C1 / 128);
        gemm_kernel<<<grid, 256>>>(nullptr, W1, b1, y1, C1, nullptr, nullptr, 0,
                                   nullptr, 0, part, 1,
                                   feat, knni, out_newxyz, 1);
    }
    reduce_kernel<<<32, C1>>>(part, red, C1);
    finalize_kernel<<<1, C1>>>(red, gamma1, beta1, scale, bias, C1);
    // 4. conv2: fused BN1+ReLU input, group-max + BN2-stats epilogue, no Y
    {
        dim3 grid(MBLK, C2 / 128);
        gemm_kernel<<<grid, 256>>>(y1, W2, b2, nullptr, C2, scale, bias, 1,
                                   gmax, 1, part, 1,
                                   nullptr, nullptr, nullptr, 0);
    }
    reduce_kernel<<<32, C2>>>(part, red, C2);
    finalize_kernel<<<1, C2>>>(red, gamma2, beta2, scale, bias, C2);
    // 5. BN2+ReLU on pre-reduced max -> output
    maxpool_kernel<<<BATCH * SPT, C2>>>(gmax, scale, bias, out_x);
}